// round 4
// baseline (speedup 1.0000x reference)
#include <cuda_runtime.h>

#define D 128
#define NMAX 500000
#define BMAX 4096

// Scratch (static __device__ globals — no allocation in kernel_launch)
__device__ float g_x2[(size_t)NMAX * D];   // 256 MB: x2 = attention*x + x
__device__ float g_sums[BMAX * D];         // segment sums
__device__ float g_cnt[BMAX];              // segment counts
__device__ float g_tg[BMAX * D];           // tanh(mean @ Wm)
__device__ int   g_is64;                   // batch dtype flag (int64 vs int32)

__device__ __forceinline__ float ftanh(float v) {
    // tanh(v) = 1 - 2/(e^{2v}+1); saturates correctly at +/-inf
    float e = __expf(2.0f * v);
    return 1.0f - __fdividef(2.0f, e + 1.0f);
}
__device__ __forceinline__ float fsigmoid(float v) {
    return __fdividef(1.0f, 1.0f + __expf(-v));
}

// ---------------------------------------------------------------------------
// K0: zero accumulators + output; detect batch element width.
// int64 little-endian => every odd 32-bit word is a zero high-half.
// int32 sorted batch => word[N-1 (odd)] ~ 2047 != 0.
// ---------------------------------------------------------------------------
__global__ void k_init(float* out, int outn, int B, const int* bw, int N) {
    int i = blockIdx.x * blockDim.x + threadIdx.x;
    int stride = gridDim.x * blockDim.x;
    for (int k = i; k < B * D; k += stride) g_sums[k] = 0.0f;
    for (int k = i; k < B; k += stride) g_cnt[k] = 0.0f;
    for (int k = i; k < outn; k += stride) out[k] = 0.0f;
    if (i == 0) {
        int io = N - 1;
        if (!(io & 1)) io--;
        g_is64 = (io >= 1 && bw[io] == 0) ? 1 : 0;
    }
}

// ---------------------------------------------------------------------------
// K1: fused per-row MLP + x2 + sorted-segment partial sums.
// Warp-per-row: lane l owns dims 4l..4l+3.
// ---------------------------------------------------------------------------
__global__ void __launch_bounds__(256) k_mlp(
    const float* __restrict__ x, const int* __restrict__ bw,
    const float* __restrict__ fc1w, const float* __restrict__ fc1b,
    const float* __restrict__ fc2w, const float* __restrict__ fc2b,
    int N, int rpw)
{
    __shared__ float4 w1s[1024];   // w1s[j*32+q] = fc1_w[j][4q..4q+3]
    __shared__ float4 w2s[1024];   // as floats: w2f[j*128+d] = fc2_w[d][j] (transposed)
    float* w2f = (float*)w2s;
    int tid = threadIdx.x;

    const float4* f1 = (const float4*)fc1w;
    for (int i = tid; i < 1024; i += blockDim.x) w1s[i] = f1[i];
    for (int i = tid; i < 4096; i += blockDim.x) {
        int d = i >> 5, j = i & 31;
        w2f[j * 128 + d] = fc2w[i];           // fc2_w is [128][32] row-major
    }
    __syncthreads();

    int lane = tid & 31;
    int warp = blockIdx.x * (blockDim.x >> 5) + (tid >> 5);
    long long r0l = (long long)warp * rpw;
    if (r0l >= N) return;
    int rs = (int)r0l;
    int re = min(N, rs + rpw);

    bool is64 = (g_is64 != 0);
    float  b1 = fc1b[lane];
    float4 b2 = ((const float4*)fc2b)[lane];

    float4 acc = make_float4(0.f, 0.f, 0.f, 0.f);
    int cur_b = -1, cnt = 0;

    for (int r = rs; r < re; r++) {
        int b = is64 ? bw[2 * r] : bw[r];
        if (b != cur_b) {
            if (cnt > 0) {
                float* dst = &g_sums[cur_b * D + lane * 4];
                atomicAdd(dst + 0, acc.x);
                atomicAdd(dst + 1, acc.y);
                atomicAdd(dst + 2, acc.z);
                atomicAdd(dst + 3, acc.w);
                if (lane == 0) atomicAdd(&g_cnt[cur_b], (float)cnt);
            }
            acc = make_float4(0.f, 0.f, 0.f, 0.f);
            cnt = 0;
            cur_b = b;
        }

        float4 xv = ((const float4*)x)[(size_t)r * 32 + lane];

        // fc1: per-lane partials over its 4 k's for all 32 hidden units
        float p[32];
        #pragma unroll
        for (int j = 0; j < 32; j++) {
            float4 w = w1s[j * 32 + lane];
            p[j] = fmaf(w.x, xv.x, fmaf(w.y, xv.y, fmaf(w.z, xv.z, w.w * xv.w)));
        }
        // reduce-scatter over lanes: 31 shfl; lane l ends with h[l] in p[0]
        #pragma unroll
        for (int step = 0; step < 5; step++) {
            const int half = 16 >> step;
            bool hi = (lane & half) != 0;
            #pragma unroll
            for (int i2 = 0; i2 < half; i2++) {
                float send = hi ? p[i2] : p[i2 + half];
                float recv = __shfl_xor_sync(0xffffffffu, send, half);
                p[i2] = (hi ? p[i2 + half] : p[i2]) + recv;
            }
        }
        float h = fmaxf(p[0] + b1, 0.0f);   // bias + ReLU, lane l holds h[l]

        // fc2: broadcast each h[j], FMA against transposed weights
        float4 a = b2;
        #pragma unroll
        for (int j = 0; j < 32; j++) {
            float hj = __shfl_sync(0xffffffffu, h, j);
            float4 w = w2s[j * 32 + lane];
            a.x = fmaf(w.x, hj, a.x);
            a.y = fmaf(w.y, hj, a.y);
            a.z = fmaf(w.z, hj, a.z);
            a.w = fmaf(w.w, hj, a.w);
        }
        a.x = ftanh(a.x); a.y = ftanh(a.y); a.z = ftanh(a.z); a.w = ftanh(a.w);

        // x2 = attention * x + x
        float4 x2v;
        x2v.x = fmaf(a.x, xv.x, xv.x);
        x2v.y = fmaf(a.y, xv.y, xv.y);
        x2v.z = fmaf(a.z, xv.z, xv.z);
        x2v.w = fmaf(a.w, xv.w, xv.w);
        ((float4*)g_x2)[(size_t)r * 32 + lane] = x2v;

        acc.x += x2v.x; acc.y += x2v.y; acc.z += x2v.z; acc.w += x2v.w;
        cnt++;
    }
    if (cnt > 0) {
        float* dst = &g_sums[cur_b * D + lane * 4];
        atomicAdd(dst + 0, acc.x);
        atomicAdd(dst + 1, acc.y);
        atomicAdd(dst + 2, acc.z);
        atomicAdd(dst + 3, acc.w);
        if (lane == 0) atomicAdd(&g_cnt[cur_b], (float)cnt);
    }
}

// ---------------------------------------------------------------------------
// K2: tg[b] = tanh( (sums[b]/max(cnt,1)) @ Wm ).  One block per segment.
// ---------------------------------------------------------------------------
__global__ void k_global(const float* __restrict__ Wm, int B) {
    int b = blockIdx.x, t = threadIdx.x;
    __shared__ float ms[128];
    float c = fmaxf(g_cnt[b], 1.0f);
    ms[t] = g_sums[b * D + t] / c;
    __syncthreads();
    float acc = 0.0f;
    #pragma unroll 16
    for (int k = 0; k < 128; k++) acc = fmaf(ms[k], Wm[k * D + t], acc);
    g_tg[b * D + t] = ftanh(acc);
}

// ---------------------------------------------------------------------------
// K3: coefs = sigmoid(<x2, tg[batch]>); out = segment_sum(coef * x2).
// Warp-per-row; tg cached in registers per segment run; sorted flush.
// ---------------------------------------------------------------------------
__global__ void __launch_bounds__(256) k_out(
    const int* __restrict__ bw, float* __restrict__ out, int N, int rpw)
{
    int tid = threadIdx.x, lane = tid & 31;
    int warp = blockIdx.x * (blockDim.x >> 5) + (tid >> 5);
    long long r0l = (long long)warp * rpw;
    if (r0l >= N) return;
    int rs = (int)r0l;
    int re = min(N, rs + rpw);

    bool is64 = (g_is64 != 0);
    float4 acc = make_float4(0.f, 0.f, 0.f, 0.f);
    float4 tgv = make_float4(0.f, 0.f, 0.f, 0.f);
    int cur_b = -1;

    for (int r = rs; r < re; r++) {
        int b = is64 ? bw[2 * r] : bw[r];
        if (b != cur_b) {
            if (cur_b >= 0) {
                float* dst = &out[cur_b * D + lane * 4];
                atomicAdd(dst + 0, acc.x);
                atomicAdd(dst + 1, acc.y);
                atomicAdd(dst + 2, acc.z);
                atomicAdd(dst + 3, acc.w);
            }
            acc = make_float4(0.f, 0.f, 0.f, 0.f);
            cur_b = b;
            tgv = ((const float4*)g_tg)[b * 32 + lane];
        }
        float4 xv = ((const float4*)g_x2)[(size_t)r * 32 + lane];
        float s = fmaf(xv.x, tgv.x, fmaf(xv.y, tgv.y, fmaf(xv.z, tgv.z, xv.w * tgv.w)));
        #pragma unroll
        for (int off = 16; off >= 1; off >>= 1)
            s += __shfl_xor_sync(0xffffffffu, s, off);
        float coef = fsigmoid(s);
        acc.x = fmaf(coef, xv.x, acc.x);
        acc.y = fmaf(coef, xv.y, acc.y);
        acc.z = fmaf(coef, xv.z, acc.z);
        acc.w = fmaf(coef, xv.w, acc.w);
    }
    if (cur_b >= 0) {
        float* dst = &out[cur_b * D + lane * 4];
        atomicAdd(dst + 0, acc.x);
        atomicAdd(dst + 1, acc.y);
        atomicAdd(dst + 2, acc.z);
        atomicAdd(dst + 3, acc.w);
    }
}

// ---------------------------------------------------------------------------
// Inputs (metadata order): x, batch, [size], Wm, fc1_w, fc1_b, fc2_w, fc2_b
// ---------------------------------------------------------------------------
extern "C" void kernel_launch(void* const* d_in, const int* in_sizes, int n_in,
                              void* d_out, int out_size)
{
    const float* x  = (const float*)d_in[0];
    const int*   bw = (const int*)d_in[1];
    int base = 2;
    if (n_in >= 8 && in_sizes[2] < 64) base = 3;   // scalar 'size' input present
    const float* Wm   = (const float*)d_in[base + 0];
    const float* fc1w = (const float*)d_in[base + 1];
    const float* fc1b = (const float*)d_in[base + 2];
    const float* fc2w = (const float*)d_in[base + 3];
    const float* fc2b = (const float*)d_in[base + 4];

    int N = in_sizes[0] / D;
    if (N > NMAX) N = NMAX;
    int B = out_size / D;
    if (B > BMAX) B = BMAX;
    float* out = (float*)d_out;

    k_init<<<256, 256>>>(out, out_size, B, bw, N);

    const int RPW = 128;                          // rows per warp (contiguous)
    int warps = (N + RPW - 1) / RPW;
    int blocks = (warps + 7) / 8;                 // 8 warps / block

    k_mlp<<<blocks, 256>>>(x, bw, fc1w, fc1b, fc2w, fc2b, N, RPW);
    k_global<<<B, 128>>>(Wm, B);
    k_out<<<blocks, 256>>>(bw, out, N, RPW);
}

// round 5
// speedup vs baseline: 3.0300x; 3.0300x over previous
#include <cuda_runtime.h>

#define D 128
#define NMAX 500000
#define BMAX 4096

// Scratch (static __device__ globals — no allocation in kernel_launch)
__device__ float g_x2[(size_t)NMAX * D];   // 256 MB: x2 = attention*x + x
__device__ float g_sums[BMAX * D];         // segment sums
__device__ float g_cnt[BMAX];              // segment counts
__device__ float g_tg[BMAX * D];           // tanh(mean @ Wm)
__device__ int   g_is64;                   // batch dtype flag (int64 vs int32)

typedef unsigned long long u64;

__device__ __forceinline__ u64 pk2(float a, float b) {
    u64 r;
    asm("mov.b64 %0,{%1,%2};" : "=l"(r)
        : "r"(__float_as_uint(a)), "r"(__float_as_uint(b)));
    return r;
}
__device__ __forceinline__ void upk2(u64 v, float& a, float& b) {
    unsigned lo, hi;
    asm("mov.b64 {%0,%1},%2;" : "=r"(lo), "=r"(hi) : "l"(v));
    a = __uint_as_float(lo); b = __uint_as_float(hi);
}
__device__ __forceinline__ u64 ffma2(u64 a, u64 b, u64 c) {
    u64 d;
    asm("fma.rn.f32x2 %0,%1,%2,%3;" : "=l"(d) : "l"(a), "l"(b), "l"(c));
    return d;
}
__device__ __forceinline__ u64 fadd2(u64 a, u64 b) {
    u64 d;
    asm("add.rn.f32x2 %0,%1,%2;" : "=l"(d) : "l"(a), "l"(b));
    return d;
}

__device__ __forceinline__ float ftanh(float v) {
    float e = __expf(2.0f * v);
    return 1.0f - __fdividef(2.0f, e + 1.0f);
}
__device__ __forceinline__ float fsigmoid(float v) {
    return __fdividef(1.0f, 1.0f + __expf(-v));
}

// ---------------------------------------------------------------------------
// K0: zero accumulators + output; detect batch element width.
// ---------------------------------------------------------------------------
__global__ void k_init(float* out, int outn, int B, const int* bw, int N) {
    int i = blockIdx.x * blockDim.x + threadIdx.x;
    int stride = gridDim.x * blockDim.x;
    for (int k = i; k < B * D; k += stride) g_sums[k] = 0.0f;
    for (int k = i; k < B; k += stride) g_cnt[k] = 0.0f;
    for (int k = i; k < outn; k += stride) out[k] = 0.0f;
    if (i == 0) {
        int io = N - 1;
        if (!(io & 1)) io--;
        g_is64 = (io >= 1 && bw[io] == 0) ? 1 : 0;
    }
}

// ---------------------------------------------------------------------------
// K1: fused MLP + x2 + sorted-segment partial sums.
// 4 rows per warp iteration. fc1: lane j computes h[j] for all 4 rows (x
// broadcast from SMEM staging, weights amortized 4x, NO reduce-scatter).
// fc2: h broadcast by shfl, lane owns 4 output dims. All MACs as f32x2.
// ---------------------------------------------------------------------------
__global__ void __launch_bounds__(128) k_mlp(
    const float* __restrict__ x, const int* __restrict__ bw,
    const float* __restrict__ fc1w, const float* __restrict__ fc1b,
    const float* __restrict__ fc2w, const float* __restrict__ fc2b,
    int N, int rpw)
{
    __shared__ float4 w1s[32 * 33];   // w1s[j*33+c] = fc1_w[j][4c..4c+3] (pad 33 kills bank conflicts)
    __shared__ float4 w2s[1024];      // as floats: w2f[j*128+d] = fc2_w[d][j] (transposed)
    __shared__ float4 xs[4 * 4 * 32]; // 4 warps x 4 rows x 32 float4 staging
    float* w2f = (float*)w2s;
    int tid = threadIdx.x;

    const float4* f1 = (const float4*)fc1w;
    for (int i = tid; i < 1024; i += 128) {
        int j = i >> 5, c = i & 31;
        w1s[j * 33 + c] = f1[i];
    }
    for (int i = tid; i < 4096; i += 128) {
        int d = i >> 5, j = i & 31;
        w2f[j * 128 + d] = fc2w[i];       // fc2_w is [128][32] row-major
    }
    __syncthreads();

    int lane = tid & 31;
    int wid = tid >> 5;
    float4* xw = &xs[wid * 128];

    int warp = blockIdx.x * 4 + wid;
    long long r0l = (long long)warp * rpw;
    if (r0l >= N) return;
    int rs = (int)r0l;
    int re = min(N, rs + rpw);

    bool is64 = (g_is64 != 0);
    float b1 = fc1b[lane];
    float4 b2v = ((const float4*)fc2b)[lane];
    u64 b2lo = pk2(b2v.x, b2v.y), b2hi = pk2(b2v.z, b2v.w);

    float4 sacc = make_float4(0.f, 0.f, 0.f, 0.f);
    int cur_b = -1, cnt = 0;

    for (int r0 = rs; r0 < re; r0 += 4) {
        // --- stage 4 rows ---
        float4 xv[4]; int bb[4];
        #pragma unroll
        for (int q = 0; q < 4; q++) {
            int rr = r0 + q; if (rr >= re) rr = re - 1;
            xv[q] = ((const float4*)x)[(size_t)rr * 32 + lane];
            xw[q * 32 + lane] = xv[q];
            bb[q] = is64 ? bw[2 * rr] : bw[rr];
        }
        __syncwarp();

        // --- fc1: lane j computes h[j] for rows 0..3 ---
        u64 acc[4][2];
        #pragma unroll
        for (int q = 0; q < 4; q++) { acc[q][0] = 0ull; acc[q][1] = 0ull; }

        #pragma unroll 8
        for (int c = 0; c < 32; c++) {
            float4 w = w1s[lane * 33 + c];
            u64 wlo = pk2(w.x, w.y), whi = pk2(w.z, w.w);
            #pragma unroll
            for (int q = 0; q < 4; q++) {
                float4 xq = xw[q * 32 + c];           // broadcast LDS.128
                acc[q][0] = ffma2(wlo, pk2(xq.x, xq.y), acc[q][0]);
                acc[q][1] = ffma2(whi, pk2(xq.z, xq.w), acc[q][1]);
            }
        }
        float h[4];
        #pragma unroll
        for (int q = 0; q < 4; q++) {
            float a, b;
            upk2(fadd2(acc[q][0], acc[q][1]), a, b);
            h[q] = fmaxf(a + b + b1, 0.0f);           // bias + ReLU; lane holds h[lane]
        }
        __syncwarp();   // xw reads done before next group's staging writes

        // --- fc2: broadcast h[j], lane owns dims 4*lane..4*lane+3 ---
        u64 a2[4][2];
        #pragma unroll
        for (int q = 0; q < 4; q++) { a2[q][0] = b2lo; a2[q][1] = b2hi; }

        #pragma unroll 8
        for (int j = 0; j < 32; j++) {
            float4 w = w2s[j * 32 + lane];
            u64 wlo = pk2(w.x, w.y), whi = pk2(w.z, w.w);
            #pragma unroll
            for (int q = 0; q < 4; q++) {
                float hj = __shfl_sync(0xffffffffu, h[q], j);
                u64 hp = pk2(hj, hj);
                a2[q][0] = ffma2(wlo, hp, a2[q][0]);
                a2[q][1] = ffma2(whi, hp, a2[q][1]);
            }
        }

        // --- epilogue: tanh, x2, store, sorted-segment accumulate ---
        #pragma unroll
        for (int q = 0; q < 4; q++) {
            int rr = r0 + q;
            if (rr >= re) break;
            float ax, ay, az, aw;
            upk2(a2[q][0], ax, ay);
            upk2(a2[q][1], az, aw);
            ax = ftanh(ax); ay = ftanh(ay); az = ftanh(az); aw = ftanh(aw);

            float4 x2v;
            x2v.x = fmaf(ax, xv[q].x, xv[q].x);
            x2v.y = fmaf(ay, xv[q].y, xv[q].y);
            x2v.z = fmaf(az, xv[q].z, xv[q].z);
            x2v.w = fmaf(aw, xv[q].w, xv[q].w);
            ((float4*)g_x2)[(size_t)rr * 32 + lane] = x2v;

            int b = bb[q];
            if (b != cur_b) {
                if (cnt > 0) {
                    float* dst = &g_sums[cur_b * D + lane * 4];
                    atomicAdd(dst + 0, sacc.x);
                    atomicAdd(dst + 1, sacc.y);
                    atomicAdd(dst + 2, sacc.z);
                    atomicAdd(dst + 3, sacc.w);
                    if (lane == 0) atomicAdd(&g_cnt[cur_b], (float)cnt);
                }
                sacc = make_float4(0.f, 0.f, 0.f, 0.f);
                cnt = 0;
                cur_b = b;
            }
            sacc.x += x2v.x; sacc.y += x2v.y; sacc.z += x2v.z; sacc.w += x2v.w;
            cnt++;
        }
    }
    if (cnt > 0) {
        float* dst = &g_sums[cur_b * D + lane * 4];
        atomicAdd(dst + 0, sacc.x);
        atomicAdd(dst + 1, sacc.y);
        atomicAdd(dst + 2, sacc.z);
        atomicAdd(dst + 3, sacc.w);
        if (lane == 0) atomicAdd(&g_cnt[cur_b], (float)cnt);
    }
}

// ---------------------------------------------------------------------------
// K2: tg[b] = tanh( (sums[b]/max(cnt,1)) @ Wm ).  One block per segment.
// ---------------------------------------------------------------------------
__global__ void k_global(const float* __restrict__ Wm, int B) {
    int b = blockIdx.x, t = threadIdx.x;
    __shared__ float ms[128];
    float c = fmaxf(g_cnt[b], 1.0f);
    ms[t] = g_sums[b * D + t] / c;
    __syncthreads();
    float acc = 0.0f;
    #pragma unroll 16
    for (int k = 0; k < 128; k++) acc = fmaf(ms[k], Wm[k * D + t], acc);
    g_tg[b * D + t] = ftanh(acc);
}

// ---------------------------------------------------------------------------
// K3: coefs = sigmoid(<x2, tg[batch]>); out = segment_sum(coef * x2).
// Warp-per-row, 4 rows pipelined; uniform-segment fast path interleaves the
// 4 shuffle-reduction chains; streaming loads for g_x2.
// ---------------------------------------------------------------------------
__global__ void __launch_bounds__(256) k_out(
    const int* __restrict__ bw, float* __restrict__ out, int N, int rpw)
{
    int tid = threadIdx.x, lane = tid & 31;
    int warp = blockIdx.x * (blockDim.x >> 5) + (tid >> 5);
    long long r0l = (long long)warp * rpw;
    if (r0l >= N) return;
    int rs = (int)r0l;
    int re = min(N, rs + rpw);

    bool is64 = (g_is64 != 0);
    const float4* x2p = (const float4*)g_x2;
    float4 acc = make_float4(0.f, 0.f, 0.f, 0.f);
    float4 tgv = make_float4(0.f, 0.f, 0.f, 0.f);
    int cur_b = -1;

    for (int r0 = rs; r0 < re; r0 += 4) {
        int m = min(4, re - r0);
        float4 xv[4]; int bb[4];
        #pragma unroll
        for (int q = 0; q < 4; q++) {
            int rr = r0 + q; if (rr >= re) rr = re - 1;
            bb[q] = is64 ? bw[2 * rr] : bw[rr];
            xv[q] = __ldcs(&x2p[(size_t)rr * 32 + lane]);
        }

        bool uni = (m == 4) & (bb[0] == cur_b) & (bb[1] == cur_b) &
                   (bb[2] == cur_b) & (bb[3] == cur_b);
        if (uni) {
            float s[4];
            #pragma unroll
            for (int q = 0; q < 4; q++)
                s[q] = fmaf(xv[q].x, tgv.x, fmaf(xv[q].y, tgv.y,
                       fmaf(xv[q].z, tgv.z, xv[q].w * tgv.w)));
            #pragma unroll
            for (int off = 16; off >= 1; off >>= 1) {
                #pragma unroll
                for (int q = 0; q < 4; q++)
                    s[q] += __shfl_xor_sync(0xffffffffu, s[q], off);
            }
            #pragma unroll
            for (int q = 0; q < 4; q++) {
                float coef = fsigmoid(s[q]);
                acc.x = fmaf(coef, xv[q].x, acc.x);
                acc.y = fmaf(coef, xv[q].y, acc.y);
                acc.z = fmaf(coef, xv[q].z, acc.z);
                acc.w = fmaf(coef, xv[q].w, acc.w);
            }
        } else {
            #pragma unroll
            for (int q = 0; q < 4; q++) {
                if (q >= m) break;
                int b = bb[q];
                if (b != cur_b) {
                    if (cur_b >= 0) {
                        float* dst = &out[cur_b * D + lane * 4];
                        atomicAdd(dst + 0, acc.x);
                        atomicAdd(dst + 1, acc.y);
                        atomicAdd(dst + 2, acc.z);
                        atomicAdd(dst + 3, acc.w);
                    }
                    acc = make_float4(0.f, 0.f, 0.f, 0.f);
                    cur_b = b;
                    tgv = ((const float4*)g_tg)[b * 32 + lane];
                }
                float s = fmaf(xv[q].x, tgv.x, fmaf(xv[q].y, tgv.y,
                          fmaf(xv[q].z, tgv.z, xv[q].w * tgv.w)));
                #pragma unroll
                for (int off = 16; off >= 1; off >>= 1)
                    s += __shfl_xor_sync(0xffffffffu, s, off);
                float coef = fsigmoid(s);
                acc.x = fmaf(coef, xv[q].x, acc.x);
                acc.y = fmaf(coef, xv[q].y, acc.y);
                acc.z = fmaf(coef, xv[q].z, acc.z);
                acc.w = fmaf(coef, xv[q].w, acc.w);
            }
        }
    }
    if (cur_b >= 0) {
        float* dst = &out[cur_b * D + lane * 4];
        atomicAdd(dst + 0, acc.x);
        atomicAdd(dst + 1, acc.y);
        atomicAdd(dst + 2, acc.z);
        atomicAdd(dst + 3, acc.w);
    }
}

// ---------------------------------------------------------------------------
// Inputs (metadata order): x, batch, [size], Wm, fc1_w, fc1_b, fc2_w, fc2_b
// ---------------------------------------------------------------------------
extern "C" void kernel_launch(void* const* d_in, const int* in_sizes, int n_in,
                              void* d_out, int out_size)
{
    const float* x  = (const float*)d_in[0];
    const int*   bw = (const int*)d_in[1];
    int base = 2;
    if (n_in >= 8 && in_sizes[2] < 64) base = 3;   // scalar 'size' input present
    const float* Wm   = (const float*)d_in[base + 0];
    const float* fc1w = (const float*)d_in[base + 1];
    const float* fc1b = (const float*)d_in[base + 2];
    const float* fc2w = (const float*)d_in[base + 3];
    const float* fc2b = (const float*)d_in[base + 4];

    int N = in_sizes[0] / D;
    if (N > NMAX) N = NMAX;
    int B = out_size / D;
    if (B > BMAX) B = BMAX;
    float* out = (float*)d_out;

    k_init<<<256, 256>>>(out, out_size, B, bw, N);

    // k_mlp: 4 warps/block (128 thr), 4-row groups, RPW multiple of 4
    const int RPW = 108;
    int warps = (N + RPW - 1) / RPW;
    int mblocks = (warps + 3) / 4;
    k_mlp<<<mblocks, 128>>>(x, bw, fc1w, fc1b, fc2w, fc2b, N, RPW);

    k_global<<<B, 128>>>(Wm, B);

    // k_out: 8 warps/block, finer RPW for occupancy
    const int RPW_OUT = 64;
    int owarps = (N + RPW_OUT - 1) / RPW_OUT;
    int oblocks = (owarps + 7) / 8;
    k_out<<<oblocks, 256>>>(bw, out, N, RPW_OUT);
}

// round 6
// speedup vs baseline: 3.2425x; 1.0701x over previous
#include <cuda_runtime.h>
#include <cuda_fp16.h>

#define D 128
#define NMAX 500000
#define BMAX 4096

// Scratch (static __device__ globals — no allocation anywhere)
__device__ __align__(16) __half g_x2h[(size_t)NMAX * D];  // 128 MB fp16 x2
__device__ float g_sums[BMAX * D];
__device__ float g_cnt[BMAX];
__device__ float g_tg[BMAX * D];
__device__ int   g_is64;

typedef unsigned long long u64;

__device__ __forceinline__ u64 pk2(float a, float b) {
    u64 r;
    asm("mov.b64 %0,{%1,%2};" : "=l"(r)
        : "r"(__float_as_uint(a)), "r"(__float_as_uint(b)));
    return r;
}
__device__ __forceinline__ void upk2(u64 v, float& a, float& b) {
    unsigned lo, hi;
    asm("mov.b64 {%0,%1},%2;" : "=r"(lo), "=r"(hi) : "l"(v));
    a = __uint_as_float(lo); b = __uint_as_float(hi);
}
__device__ __forceinline__ u64 ffma2(u64 a, u64 b, u64 c) {
    u64 d;
    asm("fma.rn.f32x2 %0,%1,%2,%3;" : "=l"(d) : "l"(a), "l"(b), "l"(c));
    return d;
}

__device__ __forceinline__ float ftanh(float v) {
    float e = __expf(2.0f * v);
    return 1.0f - __fdividef(2.0f, e + 1.0f);
}
__device__ __forceinline__ float fsigmoid(float v) {
    return __fdividef(1.0f, 1.0f + __expf(-v));
}

// ---------------------------------------------------------------------------
// K0: zero accumulators + output; detect batch element width (int64 vs int32).
// ---------------------------------------------------------------------------
__global__ void k_init(float* out, int outn, int B, const int* bw, int N) {
    int i = blockIdx.x * blockDim.x + threadIdx.x;
    int stride = gridDim.x * blockDim.x;
    for (int k = i; k < B * D; k += stride) g_sums[k] = 0.0f;
    for (int k = i; k < B; k += stride) g_cnt[k] = 0.0f;
    for (int k = i; k < outn; k += stride) out[k] = 0.0f;
    if (i == 0) {
        int io = N - 1;
        if (!(io & 1)) io--;
        g_is64 = (io >= 1 && bw[io] == 0) ? 1 : 0;
    }
}

// ---------------------------------------------------------------------------
// K1: fused MLP + x2 + sorted-segment partial sums.
// 4 rows / warp iteration, software-pipelined (next group's x prefetched
// during current group's compute). All MACs are fma.rn.f32x2 fed by
// ulonglong2 SMEM loads (aligned pairs, no packing MOVs). fc2 h-broadcast
// via SMEM stage of pre-duplicated (h,h) pairs (no SHFL).
// ---------------------------------------------------------------------------
__global__ void __launch_bounds__(128) k_mlp(
    const float* __restrict__ x, const int* __restrict__ bw,
    const float* __restrict__ fc1w, const float* __restrict__ fc1b,
    const float* __restrict__ fc2w, const float* __restrict__ fc2b,
    int N, int rpw)
{
    __shared__ float4 w1t[1024];   // w1t[c*32+j] = fc1_w[j][4c..4c+3] (transposed, coalesced per c)
    __shared__ float4 w2s[1024];   // w2f[j*128+d] = fc2_w[d][j]
    __shared__ float4 xs[4 * 128]; // 4 warps x (4 rows x 32 float4) staging
    __shared__ u64    hs[4 * 128]; // 4 warps x (4 rows x 32) duplicated h pairs
    float* w2f = (float*)w2s;
    int tid = threadIdx.x;

    const float4* f1 = (const float4*)fc1w;
    for (int i = tid; i < 1024; i += 128)
        w1t[i] = f1[(i & 31) * 32 + (i >> 5)];        // [j][c] -> [c][j]
    for (int i = tid; i < 4096; i += 128) {
        int d = i >> 5, j = i & 31;
        w2f[j * 128 + d] = fc2w[i];                   // fc2_w is [128][32] row-major
    }
    __syncthreads();

    int lane = tid & 31;
    int wid = tid >> 5;
    float4* xw = &xs[wid * 128];
    u64*    hw = &hs[wid * 128];
    const ulonglong2* w1u = (const ulonglong2*)w1t;
    const ulonglong2* w2u = (const ulonglong2*)w2s;
    const ulonglong2* xwu = (const ulonglong2*)xw;

    int warp = blockIdx.x * 4 + wid;
    long long r0l = (long long)warp * rpw;
    if (r0l >= N) return;
    int rs = (int)r0l;
    int re = min(N, rs + rpw);

    bool is64 = (g_is64 != 0);
    float b1 = fc1b[lane];
    float4 b2v = ((const float4*)fc2b)[lane];
    u64 b2lo = pk2(b2v.x, b2v.y), b2hi = pk2(b2v.z, b2v.w);

    float4 sacc = make_float4(0.f, 0.f, 0.f, 0.f);
    int cur_b = -1, cnt = 0;

    // prefetch group 0
    float4 xv[4]; int bb[4];
    #pragma unroll
    for (int q = 0; q < 4; q++) {
        int rr = rs + q; if (rr >= re) rr = re - 1;
        xv[q] = ((const float4*)x)[(size_t)rr * 32 + lane];
        bb[q] = is64 ? bw[2 * rr] : bw[rr];
    }

    for (int r0 = rs; r0 < re; r0 += 4) {
        // commit current group's x to stage
        int cb[4];
        #pragma unroll
        for (int q = 0; q < 4; q++) { xw[q * 32 + lane] = xv[q]; cb[q] = bb[q]; }
        __syncwarp();

        // prefetch next group (overlaps with MLP below)
        int rn = r0 + 4;
        if (rn < re) {
            #pragma unroll
            for (int q = 0; q < 4; q++) {
                int rr = rn + q; if (rr >= re) rr = re - 1;
                xv[q] = ((const float4*)x)[(size_t)rr * 32 + lane];
                bb[q] = is64 ? bw[2 * rr] : bw[rr];
            }
        }

        // --- fc1: lane j computes h[j] for rows 0..3 ---
        u64 acc[4][2];
        #pragma unroll
        for (int q = 0; q < 4; q++) { acc[q][0] = 0ull; acc[q][1] = 0ull; }
        #pragma unroll 8
        for (int c = 0; c < 32; c++) {
            ulonglong2 w = w1u[c * 32 + lane];        // coalesced LDS.128
            #pragma unroll
            for (int q = 0; q < 4; q++) {
                ulonglong2 xq = xwu[q * 32 + c];      // broadcast LDS.128
                acc[q][0] = ffma2(w.x, xq.x, acc[q][0]);
                acc[q][1] = ffma2(w.y, xq.y, acc[q][1]);
            }
        }
        #pragma unroll
        for (int q = 0; q < 4; q++) {
            float a, b, c2, d2;
            upk2(acc[q][0], a, b);
            upk2(acc[q][1], c2, d2);
            float hq = fmaxf(a + b + c2 + d2 + b1, 0.0f);
            hw[q * 32 + lane] = pk2(hq, hq);          // pre-duplicated pair
        }
        __syncwarp();

        // --- fc2: lane owns dims 4*lane..4*lane+3; h via broadcast LDS.64 ---
        u64 a2[4][2];
        #pragma unroll
        for (int q = 0; q < 4; q++) { a2[q][0] = b2lo; a2[q][1] = b2hi; }
        #pragma unroll 8
        for (int j = 0; j < 32; j++) {
            ulonglong2 w = w2u[j * 32 + lane];
            #pragma unroll
            for (int q = 0; q < 4; q++) {
                u64 hp = hw[q * 32 + j];              // broadcast LDS.64
                a2[q][0] = ffma2(w.x, hp, a2[q][0]);
                a2[q][1] = ffma2(w.y, hp, a2[q][1]);
            }
        }

        // --- epilogue: tanh, x2, fp16 store, sorted-segment accumulate ---
        #pragma unroll
        for (int q = 0; q < 4; q++) {
            int rr = r0 + q;
            if (rr >= re) break;
            float ax, ay, az, aw;
            upk2(a2[q][0], ax, ay);
            upk2(a2[q][1], az, aw);
            ax = ftanh(ax); ay = ftanh(ay); az = ftanh(az); aw = ftanh(aw);

            float4 xo = xw[q * 32 + lane];            // current x from stage
            float4 x2v;
            x2v.x = fmaf(ax, xo.x, xo.x);
            x2v.y = fmaf(ay, xo.y, xo.y);
            x2v.z = fmaf(az, xo.z, xo.z);
            x2v.w = fmaf(aw, xo.w, xo.w);

            __half2 p0 = __floats2half2_rn(x2v.x, x2v.y);
            __half2 p1 = __floats2half2_rn(x2v.z, x2v.w);
            float2 st;
            st.x = __uint_as_float(*(unsigned*)&p0);
            st.y = __uint_as_float(*(unsigned*)&p1);
            __stcs((float2*)&g_x2h[(size_t)rr * D + lane * 4], st);

            int b = cb[q];
            if (b != cur_b) {
                if (cnt > 0) {
                    float* dst = &g_sums[cur_b * D + lane * 4];
                    atomicAdd(dst + 0, sacc.x);
                    atomicAdd(dst + 1, sacc.y);
                    atomicAdd(dst + 2, sacc.z);
                    atomicAdd(dst + 3, sacc.w);
                    if (lane == 0) atomicAdd(&g_cnt[cur_b], (float)cnt);
                }
                sacc = make_float4(0.f, 0.f, 0.f, 0.f);
                cnt = 0;
                cur_b = b;
            }
            sacc.x += x2v.x; sacc.y += x2v.y; sacc.z += x2v.z; sacc.w += x2v.w;
            cnt++;
        }
        __syncwarp();   // protect stage before next group's STS
    }
    if (cnt > 0) {
        float* dst = &g_sums[cur_b * D + lane * 4];
        atomicAdd(dst + 0, sacc.x);
        atomicAdd(dst + 1, sacc.y);
        atomicAdd(dst + 2, sacc.z);
        atomicAdd(dst + 3, sacc.w);
        if (lane == 0) atomicAdd(&g_cnt[cur_b], (float)cnt);
    }
}

// ---------------------------------------------------------------------------
// K2: tg[b] = tanh( (sums[b]/max(cnt,1)) @ Wm ).  One block per segment.
// ---------------------------------------------------------------------------
__global__ void k_global(const float* __restrict__ Wm, int B) {
    int b = blockIdx.x, t = threadIdx.x;
    __shared__ float ms[128];
    float c = fmaxf(g_cnt[b], 1.0f);
    ms[t] = g_sums[b * D + t] / c;
    __syncthreads();
    float acc = 0.0f;
    #pragma unroll 16
    for (int k = 0; k < 128; k++) acc = fmaf(ms[k], Wm[k * D + t], acc);
    g_tg[b * D + t] = ftanh(acc);
}

// ---------------------------------------------------------------------------
// K3: coefs = sigmoid(<x2, tg[batch]>); out = segment_sum(coef * x2).
// fp16 x2 (half the DRAM traffic), 4 rows pipelined, uniform fast path.
// ---------------------------------------------------------------------------
__global__ void __launch_bounds__(256) k_out(
    const int* __restrict__ bw, float* __restrict__ out, int N, int rpw)
{
    int tid = threadIdx.x, lane = tid & 31;
    int warp = blockIdx.x * (blockDim.x >> 5) + (tid >> 5);
    long long r0l = (long long)warp * rpw;
    if (r0l >= N) return;
    int rs = (int)r0l;
    int re = min(N, rs + rpw);

    bool is64 = (g_is64 != 0);
    float4 acc = make_float4(0.f, 0.f, 0.f, 0.f);
    float4 tgv = make_float4(0.f, 0.f, 0.f, 0.f);
    int cur_b = -1;

    for (int r0 = rs; r0 < re; r0 += 4) {
        int m = min(4, re - r0);
        float4 xv[4]; int bb[4];
        #pragma unroll
        for (int q = 0; q < 4; q++) {
            int rr = r0 + q; if (rr >= re) rr = re - 1;
            bb[q] = is64 ? bw[2 * rr] : bw[rr];
            float2 u = __ldcs((const float2*)&g_x2h[(size_t)rr * D + lane * 4]);
            unsigned u0 = __float_as_uint(u.x), u1 = __float_as_uint(u.y);
            float2 f0 = __half22float2(*(__half2*)&u0);
            float2 f1 = __half22float2(*(__half2*)&u1);
            xv[q] = make_float4(f0.x, f0.y, f1.x, f1.y);
        }

        bool uni = (m == 4) & (bb[0] == cur_b) & (bb[1] == cur_b) &
                   (bb[2] == cur_b) & (bb[3] == cur_b);
        if (uni) {
            float s[4];
            #pragma unroll
            for (int q = 0; q < 4; q++)
                s[q] = fmaf(xv[q].x, tgv.x, fmaf(xv[q].y, tgv.y,
                       fmaf(xv[q].z, tgv.z, xv[q].w * tgv.w)));
            #pragma unroll
            for (int off = 16; off >= 1; off >>= 1) {
                #pragma unroll
                for (int q = 0; q < 4; q++)
                    s[q] += __shfl_xor_sync(0xffffffffu, s[q], off);
            }
            #pragma unroll
            for (int q = 0; q < 4; q++) {
                float coef = fsigmoid(s[q]);
                acc.x = fmaf(coef, xv[q].x, acc.x);
                acc.y = fmaf(coef, xv[q].y, acc.y);
                acc.z = fmaf(coef, xv[q].z, acc.z);
                acc.w = fmaf(coef, xv[q].w, acc.w);
            }
        } else {
            #pragma unroll
            for (int q = 0; q < 4; q++) {
                if (q >= m) break;
                int b = bb[q];
                if (b != cur_b) {
                    if (cur_b >= 0) {
                        float* dst = &out[cur_b * D + lane * 4];
                        atomicAdd(dst + 0, acc.x);
                        atomicAdd(dst + 1, acc.y);
                        atomicAdd(dst + 2, acc.z);
                        atomicAdd(dst + 3, acc.w);
                    }
                    acc = make_float4(0.f, 0.f, 0.f, 0.f);
                    cur_b = b;
                    tgv = ((const float4*)g_tg)[b * 32 + lane];
                }
                float s = fmaf(xv[q].x, tgv.x, fmaf(xv[q].y, tgv.y,
                          fmaf(xv[q].z, tgv.z, xv[q].w * tgv.w)));
                #pragma unroll
                for (int off = 16; off >= 1; off >>= 1)
                    s += __shfl_xor_sync(0xffffffffu, s, off);
                float coef = fsigmoid(s);
                acc.x = fmaf(coef, xv[q].x, acc.x);
                acc.y = fmaf(coef, xv[q].y, acc.y);
                acc.z = fmaf(coef, xv[q].z, acc.z);
                acc.w = fmaf(coef, xv[q].w, acc.w);
            }
        }
    }
    if (cur_b >= 0) {
        float* dst = &out[cur_b * D + lane * 4];
        atomicAdd(dst + 0, acc.x);
        atomicAdd(dst + 1, acc.y);
        atomicAdd(dst + 2, acc.z);
        atomicAdd(dst + 3, acc.w);
    }
}

// ---------------------------------------------------------------------------
// Inputs (metadata order): x, batch, [size], Wm, fc1_w, fc1_b, fc2_w, fc2_b
// ---------------------------------------------------------------------------
extern "C" void kernel_launch(void* const* d_in, const int* in_sizes, int n_in,
                              void* d_out, int out_size)
{
    const float* x  = (const float*)d_in[0];
    const int*   bw = (const int*)d_in[1];
    int base = 2;
    if (n_in >= 8 && in_sizes[2] < 64) base = 3;   // scalar 'size' input present
    const float* Wm   = (const float*)d_in[base + 0];
    const float* fc1w = (const float*)d_in[base + 1];
    const float* fc1b = (const float*)d_in[base + 2];
    const float* fc2w = (const float*)d_in[base + 3];
    const float* fc2b = (const float*)d_in[base + 4];

    int N = in_sizes[0] / D;
    if (N > NMAX) N = NMAX;
    int B = out_size / D;
    if (B > BMAX) B = BMAX;
    float* out = (float*)d_out;

    k_init<<<256, 256>>>(out, out_size, B, bw, N);

    // k_mlp: 4 warps/block, 4-row pipelined groups
    const int RPW = 72;                            // multiple of 4
    int warps = (N + RPW - 1) / RPW;
    int mblocks = (warps + 3) / 4;
    k_mlp<<<mblocks, 128>>>(x, bw, fc1w, fc1b, fc2w, fc2b, N, RPW);

    k_global<<<B, 128>>>(Wm, B);

    const int RPW_OUT = 64;
    int owarps = (N + RPW_OUT - 1) / RPW_OUT;
    int oblocks = (owarps + 7) / 8;
    k_out<<<oblocks, 256>>>(bw, out, N, RPW_OUT);
}

// round 7
// speedup vs baseline: 3.9498x; 1.2181x over previous
#include <cuda_runtime.h>
#include <cuda_fp16.h>

#define D 128
#define NMAX 500000
#define BMAX 4096

// Scratch (static __device__ globals — no allocation anywhere)
__device__ __align__(16) __half g_x2h[(size_t)NMAX * D];  // 128 MB fp16 x2
__device__ float g_sums[BMAX * D];
__device__ float g_cnt[BMAX];
__device__ float g_tg[BMAX * D];
__device__ int   g_is64;

typedef unsigned long long u64;

__device__ __forceinline__ u64 pk2(float a, float b) {
    u64 r;
    asm("mov.b64 %0,{%1,%2};" : "=l"(r)
        : "r"(__float_as_uint(a)), "r"(__float_as_uint(b)));
    return r;
}
__device__ __forceinline__ void upk2(u64 v, float& a, float& b) {
    unsigned lo, hi;
    asm("mov.b64 {%0,%1},%2;" : "=r"(lo), "=r"(hi) : "l"(v));
    a = __uint_as_float(lo); b = __uint_as_float(hi);
}
__device__ __forceinline__ u64 ffma2(u64 a, u64 b, u64 c) {
    u64 d;
    asm("fma.rn.f32x2 %0,%1,%2,%3;" : "=l"(d) : "l"(a), "l"(b), "l"(c));
    return d;
}

__device__ __forceinline__ void cpa16(const void* smem_dst, const void* gmem_src) {
    unsigned s = (unsigned)__cvta_generic_to_shared(smem_dst);
    asm volatile("cp.async.cg.shared.global [%0],[%1],16;" :: "r"(s), "l"(gmem_src));
}
#define CP_COMMIT() asm volatile("cp.async.commit_group;")
#define CP_WAIT1()  asm volatile("cp.async.wait_group 1;")
#define CP_WAIT0()  asm volatile("cp.async.wait_group 0;")

__device__ __forceinline__ float ftanh(float v) {
    float e = __expf(2.0f * v);
    return 1.0f - __fdividef(2.0f, e + 1.0f);
}
__device__ __forceinline__ float fsigmoid(float v) {
    return __fdividef(1.0f, 1.0f + __expf(-v));
}

// ---------------------------------------------------------------------------
// K0: zero accumulators + output; detect batch element width (int64 vs int32).
// ---------------------------------------------------------------------------
__global__ void k_init(float* out, int outn, int B, const int* bw, int N) {
    int i = blockIdx.x * blockDim.x + threadIdx.x;
    int stride = gridDim.x * blockDim.x;
    for (int k = i; k < B * D; k += stride) g_sums[k] = 0.0f;
    for (int k = i; k < B; k += stride) g_cnt[k] = 0.0f;
    for (int k = i; k < outn; k += stride) out[k] = 0.0f;
    if (i == 0) {
        int io = N - 1;
        if (!(io & 1)) io--;
        g_is64 = (io >= 1 && bw[io] == 0) ? 1 : 0;
    }
}

// ---------------------------------------------------------------------------
// K1: fused MLP + x2 + sorted-segment partial sums.
// 8 rows / warp iteration: weights amortized 8x. x prefetched by double-
// buffered cp.async (no register prefetch). fc1: lane j computes h[j] for
// all 8 rows (x broadcast LDS). fc2: h via pre-duplicated (h,h) LDS.64
// broadcast. All MACs fma.rn.f32x2. Dynamic smem 112KB, 2 blocks/SM.
// ---------------------------------------------------------------------------
__global__ void __launch_bounds__(256, 2) k_mlp(
    const float* __restrict__ x, const int* __restrict__ bw,
    const float* __restrict__ fc1w, const float* __restrict__ fc1b,
    const float* __restrict__ fc2w, const float* __restrict__ fc2b,
    int N, int rpw)
{
    extern __shared__ char sm_[];
    float4* w1t = (float4*)sm_;            // 1024 f4: w1t[c*32+j] = fc1_w[j][4c..]
    float4* w2s = w1t + 1024;              // 1024 f4: w2f[j*128+d] = fc2_w[d][j]
    float4* xs  = w2s + 1024;              // 8 warps x 2 bufs x 8 rows x 32 f4
    u64*    hs  = (u64*)(xs + 8 * 512);    // 8 warps x 8 rows x 32 u64

    int tid = threadIdx.x;
    const float4* f1 = (const float4*)fc1w;
    for (int i = tid; i < 1024; i += 256)
        w1t[i] = f1[(i & 31) * 32 + (i >> 5)];        // [j][c] -> [c][j]
    float* w2f = (float*)w2s;
    for (int i = tid; i < 4096; i += 256) {
        int d = i >> 5, j = i & 31;
        w2f[j * 128 + d] = fc2w[i];                   // fc2_w [128][32] row-major
    }
    __syncthreads();

    int lane = tid & 31;
    int wid = tid >> 5;
    float4* xw0 = xs + wid * 512;          // two 256-f4 buffers
    u64*    hw  = hs + wid * 256;
    const ulonglong2* w1u = (const ulonglong2*)w1t;
    const ulonglong2* w2u = (const ulonglong2*)w2s;

    int warp = blockIdx.x * 8 + wid;
    long long r0l = (long long)warp * rpw;
    if (r0l >= N) return;
    int rs = (int)r0l;
    int re = min(N, rs + rpw);

    bool is64 = (g_is64 != 0);
    float b1 = fc1b[lane];
    float4 b2v = ((const float4*)fc2b)[lane];
    u64 b2lo = pk2(b2v.x, b2v.y), b2hi = pk2(b2v.z, b2v.w);

    float4 sacc = make_float4(0.f, 0.f, 0.f, 0.f);
    int cur_b = -1, cnt = 0;

    // prologue: issue group 0 into buf 0
    #pragma unroll
    for (int q = 0; q < 8; q++) {
        int rr = rs + q; if (rr >= re) rr = re - 1;
        cpa16(&xw0[q * 32 + lane], &x[(size_t)rr * D + lane * 4]);
    }
    CP_COMMIT();

    int buf = 0;
    for (int r0 = rs; r0 < re; r0 += 8) {
        // issue next group into other buffer, then wait for current
        if (r0 + 8 < re) {
            float4* nb = xw0 + (buf ^ 1) * 256;
            #pragma unroll
            for (int q = 0; q < 8; q++) {
                int rr = r0 + 8 + q; if (rr >= re) rr = re - 1;
                cpa16(&nb[q * 32 + lane], &x[(size_t)rr * D + lane * 4]);
            }
            CP_COMMIT();
            CP_WAIT1();
        } else {
            CP_WAIT0();
        }
        __syncwarp();
        const float4* xw = xw0 + buf * 256;
        const ulonglong2* xwu = (const ulonglong2*)xw;
        buf ^= 1;

        // batch ids for this group
        int cb[8];
        #pragma unroll
        for (int q = 0; q < 8; q++) {
            int rr = r0 + q; if (rr >= re) rr = re - 1;
            cb[q] = is64 ? bw[2 * rr] : bw[rr];
        }

        // --- fc1: lane j computes h[j] for rows 0..7 ---
        u64 a0[8], a1[8];
        #pragma unroll
        for (int q = 0; q < 8; q++) { a0[q] = 0ull; a1[q] = 0ull; }
        #pragma unroll 4
        for (int c = 0; c < 32; c++) {
            ulonglong2 w = w1u[c * 32 + lane];        // coalesced LDS.128
            #pragma unroll
            for (int q = 0; q < 8; q++) {
                ulonglong2 xq = xwu[q * 32 + c];      // broadcast LDS.128
                a0[q] = ffma2(w.x, xq.x, a0[q]);
                a1[q] = ffma2(w.y, xq.y, a1[q]);
            }
        }
        __syncwarp();   // all lanes done reading hw from previous group
        #pragma unroll
        for (int q = 0; q < 8; q++) {
            float a, b, c2, d2;
            upk2(a0[q], a, b);
            upk2(a1[q], c2, d2);
            float hq = fmaxf(a + b + c2 + d2 + b1, 0.0f);
            hw[q * 32 + lane] = pk2(hq, hq);          // pre-duplicated pair
        }
        __syncwarp();

        // --- fc2: lane owns dims 4*lane..4*lane+3 ---
        u64 o0[8], o1[8];
        #pragma unroll
        for (int q = 0; q < 8; q++) { o0[q] = b2lo; o1[q] = b2hi; }
        #pragma unroll 4
        for (int j = 0; j < 32; j++) {
            ulonglong2 w = w2u[j * 32 + lane];
            #pragma unroll
            for (int q = 0; q < 8; q++) {
                u64 hp = hw[q * 32 + j];              // broadcast LDS.64
                o0[q] = ffma2(w.x, hp, o0[q]);
                o1[q] = ffma2(w.y, hp, o1[q]);
            }
        }

        // --- epilogue: tanh, x2, fp16 store, sorted-segment accumulate ---
        #pragma unroll
        for (int q = 0; q < 8; q++) {
            int rr = r0 + q;
            if (rr >= re) break;
            float ax, ay, az, aw;
            upk2(o0[q], ax, ay);
            upk2(o1[q], az, aw);
            ax = ftanh(ax); ay = ftanh(ay); az = ftanh(az); aw = ftanh(aw);

            float4 xo = xw[q * 32 + lane];
            float4 x2v;
            x2v.x = fmaf(ax, xo.x, xo.x);
            x2v.y = fmaf(ay, xo.y, xo.y);
            x2v.z = fmaf(az, xo.z, xo.z);
            x2v.w = fmaf(aw, xo.w, xo.w);

            __half2 p0 = __floats2half2_rn(x2v.x, x2v.y);
            __half2 p1 = __floats2half2_rn(x2v.z, x2v.w);
            float2 st;
            st.x = __uint_as_float(*(unsigned*)&p0);
            st.y = __uint_as_float(*(unsigned*)&p1);
            __stcs((float2*)&g_x2h[(size_t)rr * D + lane * 4], st);

            int b = cb[q];
            if (b != cur_b) {
                if (cnt > 0) {
                    float* dst = &g_sums[cur_b * D + lane * 4];
                    atomicAdd(dst + 0, sacc.x);
                    atomicAdd(dst + 1, sacc.y);
                    atomicAdd(dst + 2, sacc.z);
                    atomicAdd(dst + 3, sacc.w);
                    if (lane == 0) atomicAdd(&g_cnt[cur_b], (float)cnt);
                }
                sacc = make_float4(0.f, 0.f, 0.f, 0.f);
                cnt = 0;
                cur_b = b;
            }
            sacc.x += x2v.x; sacc.y += x2v.y; sacc.z += x2v.z; sacc.w += x2v.w;
            cnt++;
        }
    }
    if (cnt > 0) {
        float* dst = &g_sums[cur_b * D + lane * 4];
        atomicAdd(dst + 0, sacc.x);
        atomicAdd(dst + 1, sacc.y);
        atomicAdd(dst + 2, sacc.z);
        atomicAdd(dst + 3, sacc.w);
        if (lane == 0) atomicAdd(&g_cnt[cur_b], (float)cnt);
    }
}

// ---------------------------------------------------------------------------
// K2: tg[b] = tanh( (sums[b]/max(cnt,1)) @ Wm ).  One block per segment.
// ---------------------------------------------------------------------------
__global__ void k_global(const float* __restrict__ Wm, int B) {
    int b = blockIdx.x, t = threadIdx.x;
    __shared__ float ms[128];
    float c = fmaxf(g_cnt[b], 1.0f);
    ms[t] = g_sums[b * D + t] / c;
    __syncthreads();
    float acc = 0.0f;
    #pragma unroll 16
    for (int k = 0; k < 128; k++) acc = fmaf(ms[k], Wm[k * D + t], acc);
    g_tg[b * D + t] = ftanh(acc);
}

// ---------------------------------------------------------------------------
// K3: coefs = sigmoid(<x2, tg[batch]>); out = segment_sum(coef * x2).
// fp16 x2, 4 rows pipelined, uniform fast path.
// ---------------------------------------------------------------------------
__global__ void __launch_bounds__(256) k_out(
    const int* __restrict__ bw, float* __restrict__ out, int N, int rpw)
{
    int tid = threadIdx.x, lane = tid & 31;
    int warp = blockIdx.x * (blockDim.x >> 5) + (tid >> 5);
    long long r0l = (long long)warp * rpw;
    if (r0l >= N) return;
    int rs = (int)r0l;
    int re = min(N, rs + rpw);

    bool is64 = (g_is64 != 0);
    float4 acc = make_float4(0.f, 0.f, 0.f, 0.f);
    float4 tgv = make_float4(0.f, 0.f, 0.f, 0.f);
    int cur_b = -1;

    for (int r0 = rs; r0 < re; r0 += 4) {
        int m = min(4, re - r0);
        float4 xv[4]; int bb[4];
        #pragma unroll
        for (int q = 0; q < 4; q++) {
            int rr = r0 + q; if (rr >= re) rr = re - 1;
            bb[q] = is64 ? bw[2 * rr] : bw[rr];
            float2 u = __ldcs((const float2*)&g_x2h[(size_t)rr * D + lane * 4]);
            unsigned u0 = __float_as_uint(u.x), u1 = __float_as_uint(u.y);
            float2 f0 = __half22float2(*(__half2*)&u0);
            float2 f1 = __half22float2(*(__half2*)&u1);
            xv[q] = make_float4(f0.x, f0.y, f1.x, f1.y);
        }

        bool uni = (m == 4) & (bb[0] == cur_b) & (bb[1] == cur_b) &
                   (bb[2] == cur_b) & (bb[3] == cur_b);
        if (uni) {
            float s[4];
            #pragma unroll
            for (int q = 0; q < 4; q++)
                s[q] = fmaf(xv[q].x, tgv.x, fmaf(xv[q].y, tgv.y,
                       fmaf(xv[q].z, tgv.z, xv[q].w * tgv.w)));
            #pragma unroll
            for (int off = 16; off >= 1; off >>= 1) {
                #pragma unroll
                for (int q = 0; q < 4; q++)
                    s[q] += __shfl_xor_sync(0xffffffffu, s[q], off);
            }
            #pragma unroll
            for (int q = 0; q < 4; q++) {
                float coef = fsigmoid(s[q]);
                acc.x = fmaf(coef, xv[q].x, acc.x);
                acc.y = fmaf(coef, xv[q].y, acc.y);
                acc.z = fmaf(coef, xv[q].z, acc.z);
                acc.w = fmaf(coef, xv[q].w, acc.w);
            }
        } else {
            #pragma unroll
            for (int q = 0; q < 4; q++) {
                if (q >= m) break;
                int b = bb[q];
                if (b != cur_b) {
                    if (cur_b >= 0) {
                        float* dst = &out[cur_b * D + lane * 4];
                        atomicAdd(dst + 0, acc.x);
                        atomicAdd(dst + 1, acc.y);
                        atomicAdd(dst + 2, acc.z);
                        atomicAdd(dst + 3, acc.w);
                    }
                    acc = make_float4(0.f, 0.f, 0.f, 0.f);
                    cur_b = b;
                    tgv = ((const float4*)g_tg)[b * 32 + lane];
                }
                float s = fmaf(xv[q].x, tgv.x, fmaf(xv[q].y, tgv.y,
                          fmaf(xv[q].z, tgv.z, xv[q].w * tgv.w)));
                #pragma unroll
                for (int off = 16; off >= 1; off >>= 1)
                    s += __shfl_xor_sync(0xffffffffu, s, off);
                float coef = fsigmoid(s);
                acc.x = fmaf(coef, xv[q].x, acc.x);
                acc.y = fmaf(coef, xv[q].y, acc.y);
                acc.z = fmaf(coef, xv[q].z, acc.z);
                acc.w = fmaf(coef, xv[q].w, acc.w);
            }
        }
    }
    if (cur_b >= 0) {
        float* dst = &out[cur_b * D + lane * 4];
        atomicAdd(dst + 0, acc.x);
        atomicAdd(dst + 1, acc.y);
        atomicAdd(dst + 2, acc.z);
        atomicAdd(dst + 3, acc.w);
    }
}

// ---------------------------------------------------------------------------
// Inputs (metadata order): x, batch, [size], Wm, fc1_w, fc1_b, fc2_w, fc2_b
// ---------------------------------------------------------------------------
extern "C" void kernel_launch(void* const* d_in, const int* in_sizes, int n_in,
                              void* d_out, int out_size)
{
    const float* x  = (const float*)d_in[0];
    const int*   bw = (const int*)d_in[1];
    int base = 2;
    if (n_in >= 8 && in_sizes[2] < 64) base = 3;   // scalar 'size' input present
    const float* Wm   = (const float*)d_in[base + 0];
    const float* fc1w = (const float*)d_in[base + 1];
    const float* fc1b = (const float*)d_in[base + 2];
    const float* fc2w = (const float*)d_in[base + 3];
    const float* fc2b = (const float*)d_in[base + 4];

    int N = in_sizes[0] / D;
    if (N > NMAX) N = NMAX;
    int B = out_size / D;
    if (B > BMAX) B = BMAX;
    float* out = (float*)d_out;

    k_init<<<256, 256>>>(out, out_size, B, bw, N);

    // k_mlp: 8 warps/block, 8-row cp.async-pipelined groups, 112KB dyn smem
    const size_t MSMEM = (size_t)(1024 + 1024 + 8 * 512) * sizeof(float4)
                       + (size_t)(8 * 256) * sizeof(u64);   // 114688 B
    static int attr_done = 0;
    if (!attr_done) {
        cudaFuncSetAttribute(k_mlp, cudaFuncAttributeMaxDynamicSharedMemorySize,
                             (int)MSMEM);
        attr_done = 1;
    }
    const int RPW = 216;                           // multiple of 8
    int warps = (N + RPW - 1) / RPW;
    int mblocks = (warps + 7) / 8;
    k_mlp<<<mblocks, 256, MSMEM>>>(x, bw, fc1w, fc1b, fc2w, fc2b, N, RPW);

    k_global<<<B, 128>>>(Wm, B);

    const int RPW_OUT = 48;
    int owarps = (N + RPW_OUT - 1) / RPW_OUT;
    int oblocks = (owarps + 7) / 8;
    k_out<<<oblocks, 256>>>(bw, out, N, RPW_OUT);
}

// round 8
// speedup vs baseline: 6.7870x; 1.7183x over previous
#include <cuda_runtime.h>
#include <cuda_fp16.h>

#define D 128
#define NMAX 500000
#define BMAX 4096
#define XS_STRIDE 132   // padded floats per staged row (bank spread)

// Scratch (static __device__ globals — no allocation anywhere)
__device__ __align__(16) __half g_x2h[(size_t)NMAX * D];  // 128 MB fp16 x2
__device__ float g_sums[BMAX * D];
__device__ float g_cnt[BMAX];
__device__ float g_tg[BMAX * D];
__device__ int   g_is64;

__device__ __forceinline__ float ftanh(float v) {
    float e = __expf(2.0f * v);
    return 1.0f - __fdividef(2.0f, e + 1.0f);
}
__device__ __forceinline__ float fsigmoid(float v) {
    return __fdividef(1.0f, 1.0f + __expf(-v));
}

__device__ __forceinline__ void cpa16(const void* smem_dst, const void* gmem_src) {
    unsigned s = (unsigned)__cvta_generic_to_shared(smem_dst);
    asm volatile("cp.async.cg.shared.global [%0],[%1],16;" :: "r"(s), "l"(gmem_src));
}
#define CP_COMMIT() asm volatile("cp.async.commit_group;")
#define CP_WAIT0()  asm volatile("cp.async.wait_group 0;")

// m16n8k16 row.col f32 += f16*f16
__device__ __forceinline__ void mma16816(float c[4], const unsigned a[4], const unsigned b[2]) {
    asm volatile(
        "mma.sync.aligned.m16n8k16.row.col.f32.f16.f16.f32 "
        "{%0,%1,%2,%3},{%4,%5,%6,%7},{%8,%9},{%0,%1,%2,%3};"
        : "+f"(c[0]), "+f"(c[1]), "+f"(c[2]), "+f"(c[3])
        : "r"(a[0]), "r"(a[1]), "r"(a[2]), "r"(a[3]), "r"(b[0]), "r"(b[1]));
}

__device__ __forceinline__ unsigned packh2(float a, float b) {
    __half2 h = __floats2half2_rn(a, b);
    return *(unsigned*)&h;
}

// ---------------------------------------------------------------------------
// K0: zero accumulators + output; detect batch element width (int64 vs int32).
// ---------------------------------------------------------------------------
__global__ void k_init(float* out, int outn, int B, const int* bw, int N) {
    int i = blockIdx.x * blockDim.x + threadIdx.x;
    int stride = gridDim.x * blockDim.x;
    for (int k = i; k < B * D; k += stride) g_sums[k] = 0.0f;
    for (int k = i; k < B; k += stride) g_cnt[k] = 0.0f;
    for (int k = i; k < outn; k += stride) out[k] = 0.0f;
    if (i == 0) {
        int io = N - 1;
        if (!(io & 1)) io--;
        g_is64 = (io >= 1 && bw[io] == 0) ? 1 : 0;
    }
}

// ---------------------------------------------------------------------------
// K1: fused MLP + x2 + sorted-segment partial sums via HMMA m16n8k16.
// 16 rows per warp-group. Weights pre-packed into fragment-layout SMEM.
// fc1 C-frags map directly to fc2 A-frags (no shuffles, no H roundtrip).
// x staged fp32 (cp.async, stride-132 pad); epilogue residual fp32-exact.
// ---------------------------------------------------------------------------
__global__ void __launch_bounds__(256, 2) k_mlp(
    const float* __restrict__ x, const int* __restrict__ bw,
    const float* __restrict__ fc1w, const float* __restrict__ fc1b,
    const float* __restrict__ fc2w, const float* __restrict__ fc2b,
    int N, int rpw)
{
    extern __shared__ char sm_[];
    uint2* w1f = (uint2*)sm_;                 // 1024 frags: [kt*4+nt][lane]
    uint2* w2f = w1f + 1024;                  // 1024 frags: [kt2*16+nt][lane]
    float* xs_all = (float*)(w2f + 1024);     // 8 warps * 16 * 132 floats

    int tid = threadIdx.x;
    // Build weight fragments (B-frag layout, col-major B = W[n][k])
    for (int e = tid; e < 1024; e += 256) {
        int tile = e >> 5, ln = e & 31;
        int gg = ln >> 2, mm = ln & 3;
        {   // fc1: tile = kt*4 + nt ; B[k][n] = fc1_w[n][k], n = nt*8+g, k = kt*16+2m..
            int kt = tile >> 2, nt = tile & 3;
            const float* wr = fc1w + (nt * 8 + gg) * 128 + kt * 16 + 2 * mm;
            w1f[e] = make_uint2(packh2(wr[0], wr[1]), packh2(wr[8], wr[9]));
        }
        {   // fc2: tile = kt2*16 + nt ; B[k][n] = fc2_w[n][k], n = nt*8+g, k = kt2*16+2m..
            int kt2 = tile >> 4, nt = tile & 15;
            const float* wr = fc2w + (nt * 8 + gg) * 32 + kt2 * 16 + 2 * mm;
            w2f[e] = make_uint2(packh2(wr[0], wr[1]), packh2(wr[8], wr[9]));
        }
    }
    __syncthreads();

    int lane = tid & 31, wid = tid >> 5;
    int g = lane >> 2, m = lane & 3;
    float* xs = xs_all + wid * (16 * XS_STRIDE);

    int warp = blockIdx.x * 8 + wid;
    long long r0l = (long long)warp * rpw;
    if (r0l >= N) return;
    int rs = (int)r0l;
    int re = min(N, rs + rpw);

    bool is64 = (g_is64 != 0);
    // fc1 bias per lane: b1v[nt*2+i] = fc1_b[nt*8 + 2m + i]
    float b1v[8];
    #pragma unroll
    for (int nt = 0; nt < 4; nt++) {
        float2 t = *(const float2*)&fc1b[nt * 8 + 2 * m];
        b1v[nt * 2] = t.x; b1v[nt * 2 + 1] = t.y;
    }

    float sacc[32];
    #pragma unroll
    for (int i = 0; i < 32; i++) sacc[i] = 0.0f;
    int cur_b = -1, cnt = 0;

    // prologue: cp.async group 0 (lane loads its 16B chunk of every row)
    #pragma unroll
    for (int q = 0; q < 16; q++) {
        int rr = rs + q; if (rr >= re) rr = re - 1;
        cpa16(&xs[q * XS_STRIDE + lane * 4], &x[(size_t)rr * D + lane * 4]);
    }
    CP_COMMIT();

    for (int r0 = rs; r0 < re; r0 += 16) {
        CP_WAIT0();
        __syncwarp();

        // batch ids (lanes 0..15 hold row lane's id)
        int mybat = 0;
        if (lane < 16) {
            int rr = r0 + lane; if (rr >= re) rr = re - 1;
            mybat = is64 ? bw[2 * rr] : bw[rr];
        }
        int nvalid = min(16, re - r0);
        int b_first = __shfl_sync(0xffffffffu, mybat, 0);
        int b_last  = __shfl_sync(0xffffffffu, mybat, nvalid - 1);
        bool mixed = (b_first != b_last);     // sorted => ends equal <=> uniform

        // flush on segment change (warp-uniform condition)
        if ((mixed || b_first != cur_b) && cnt > 0) {
            #pragma unroll
            for (int i = 0; i < 32; i++) {
                sacc[i] += __shfl_xor_sync(0xffffffffu, sacc[i], 4);
                sacc[i] += __shfl_xor_sync(0xffffffffu, sacc[i], 8);
                sacc[i] += __shfl_xor_sync(0xffffffffu, sacc[i], 16);
            }
            if (lane < 4) {
                #pragma unroll
                for (int nt = 0; nt < 16; nt++) {
                    atomicAdd(&g_sums[cur_b * D + nt * 8 + 2 * lane],     sacc[nt * 2]);
                    atomicAdd(&g_sums[cur_b * D + nt * 8 + 2 * lane + 1], sacc[nt * 2 + 1]);
                }
            }
            if (lane == 0) atomicAdd(&g_cnt[cur_b], (float)cnt);
            #pragma unroll
            for (int i = 0; i < 32; i++) sacc[i] = 0.0f;
            cnt = 0;
        }
        if (!mixed) { cur_b = b_first; cnt += nvalid; }
        else        { cur_b = -1; }

        // --- fc1: C1[nt] = X @ W1^T (tile nt) ---
        float C1[4][4];
        #pragma unroll
        for (int nt = 0; nt < 4; nt++)
            #pragma unroll
            for (int i = 0; i < 4; i++) C1[nt][i] = 0.0f;

        #pragma unroll
        for (int kt = 0; kt < 8; kt++) {
            const float* xb = xs + kt * 16 + 2 * m;
            float2 p0 = *(const float2*)&xb[g * XS_STRIDE];
            float2 p1 = *(const float2*)&xb[(g + 8) * XS_STRIDE];
            float2 p2 = *(const float2*)&xb[g * XS_STRIDE + 8];
            float2 p3 = *(const float2*)&xb[(g + 8) * XS_STRIDE + 8];
            unsigned A[4];
            A[0] = packh2(p0.x, p0.y);
            A[1] = packh2(p1.x, p1.y);
            A[2] = packh2(p2.x, p2.y);
            A[3] = packh2(p3.x, p3.y);
            #pragma unroll
            for (int nt = 0; nt < 4; nt++) {
                uint2 bf = w1f[(kt * 4 + nt) * 32 + lane];
                unsigned B[2] = { bf.x, bf.y };
                mma16816(C1[nt], A, B);
            }
        }

        // --- bias + ReLU + direct C->A repack for fc2 ---
        unsigned A2[2][4];
        #pragma unroll
        for (int kt2 = 0; kt2 < 2; kt2++) {
            int nta = 2 * kt2, ntb = 2 * kt2 + 1;
            float ha0 = fmaxf(C1[nta][0] + b1v[nta * 2],     0.0f);
            float ha1 = fmaxf(C1[nta][1] + b1v[nta * 2 + 1], 0.0f);
            float ha2 = fmaxf(C1[nta][2] + b1v[nta * 2],     0.0f);
            float ha3 = fmaxf(C1[nta][3] + b1v[nta * 2 + 1], 0.0f);
            float hb0 = fmaxf(C1[ntb][0] + b1v[ntb * 2],     0.0f);
            float hb1 = fmaxf(C1[ntb][1] + b1v[ntb * 2 + 1], 0.0f);
            float hb2 = fmaxf(C1[ntb][2] + b1v[ntb * 2],     0.0f);
            float hb3 = fmaxf(C1[ntb][3] + b1v[ntb * 2 + 1], 0.0f);
            A2[kt2][0] = packh2(ha0, ha1);
            A2[kt2][1] = packh2(ha2, ha3);
            A2[kt2][2] = packh2(hb0, hb1);
            A2[kt2][3] = packh2(hb2, hb3);
        }

        // --- fc2 (two halves of 8 n-tiles) + epilogue ---
        bool vg  = (r0 + g)     < re;
        bool vg8 = (r0 + g + 8) < re;
        int bg = 0, bg8 = 0;
        if (mixed) {
            bg  = __shfl_sync(0xffffffffu, mybat, g);
            bg8 = __shfl_sync(0xffffffffu, mybat, g + 8);
        }

        #pragma unroll
        for (int hf = 0; hf < 2; hf++) {
            float C2[8][4];
            #pragma unroll
            for (int nn = 0; nn < 8; nn++) {
                int nt = hf * 8 + nn;
                float2 b2 = *(const float2*)&fc2b[nt * 8 + 2 * m];
                C2[nn][0] = b2.x; C2[nn][1] = b2.y;
                C2[nn][2] = b2.x; C2[nn][3] = b2.y;
                #pragma unroll
                for (int kt2 = 0; kt2 < 2; kt2++) {
                    uint2 bf = w2f[(kt2 * 16 + nt) * 32 + lane];
                    unsigned B[2] = { bf.x, bf.y };
                    mma16816(C2[nn], A2[kt2], B);
                }
            }
            #pragma unroll
            for (int nn = 0; nn < 8; nn++) {
                int nt = hf * 8 + nn;
                int dim = nt * 8 + 2 * m;
                float a0 = ftanh(C2[nn][0]), a1 = ftanh(C2[nn][1]);
                float a2 = ftanh(C2[nn][2]), a3 = ftanh(C2[nn][3]);
                float2 xg  = *(const float2*)&xs[g * XS_STRIDE + dim];
                float2 xg8 = *(const float2*)&xs[(g + 8) * XS_STRIDE + dim];
                float v0 = fmaf(a0, xg.x,  xg.x);
                float v1 = fmaf(a1, xg.y,  xg.y);
                float v2 = fmaf(a2, xg8.x, xg8.x);
                float v3 = fmaf(a3, xg8.y, xg8.y);
                if (vg) {
                    __half2 hh = __floats2half2_rn(v0, v1);
                    *(__half2*)&g_x2h[(size_t)(r0 + g) * D + dim] = hh;
                }
                if (vg8) {
                    __half2 hh = __floats2half2_rn(v2, v3);
                    *(__half2*)&g_x2h[(size_t)(r0 + g + 8) * D + dim] = hh;
                }
                if (!mixed) {
                    sacc[nt * 2]     += (vg ? v0 : 0.0f) + (vg8 ? v2 : 0.0f);
                    sacc[nt * 2 + 1] += (vg ? v1 : 0.0f) + (vg8 ? v3 : 0.0f);
                } else {
                    if (vg) {
                        atomicAdd(&g_sums[bg * D + dim],     v0);
                        atomicAdd(&g_sums[bg * D + dim + 1], v1);
                    }
                    if (vg8) {
                        atomicAdd(&g_sums[bg8 * D + dim],     v2);
                        atomicAdd(&g_sums[bg8 * D + dim + 1], v3);
                    }
                }
            }
        }
        if (mixed && lane < nvalid) atomicAdd(&g_cnt[mybat], 1.0f);

        // issue next group's cp.async (all xs reads complete)
        __syncwarp();
        if (r0 + 16 < re) {
            #pragma unroll
            for (int q = 0; q < 16; q++) {
                int rr = r0 + 16 + q; if (rr >= re) rr = re - 1;
                cpa16(&xs[q * XS_STRIDE + lane * 4], &x[(size_t)rr * D + lane * 4]);
            }
            CP_COMMIT();
        }
    }

    // final flush
    if (cnt > 0) {
        #pragma unroll
        for (int i = 0; i < 32; i++) {
            sacc[i] += __shfl_xor_sync(0xffffffffu, sacc[i], 4);
            sacc[i] += __shfl_xor_sync(0xffffffffu, sacc[i], 8);
            sacc[i] += __shfl_xor_sync(0xffffffffu, sacc[i], 16);
        }
        if (lane < 4) {
            #pragma unroll
            for (int nt = 0; nt < 16; nt++) {
                atomicAdd(&g_sums[cur_b * D + nt * 8 + 2 * lane],     sacc[nt * 2]);
                atomicAdd(&g_sums[cur_b * D + nt * 8 + 2 * lane + 1], sacc[nt * 2 + 1]);
            }
        }
        if (lane == 0) atomicAdd(&g_cnt[cur_b], (float)cnt);
    }
}

// ---------------------------------------------------------------------------
// K2: tg[b] = tanh( (sums[b]/max(cnt,1)) @ Wm ).  One block per segment.
// ---------------------------------------------------------------------------
__global__ void k_global(const float* __restrict__ Wm, int B) {
    int b = blockIdx.x, t = threadIdx.x;
    __shared__ float ms[128];
    float c = fmaxf(g_cnt[b], 1.0f);
    ms[t] = g_sums[b * D + t] / c;
    __syncthreads();
    float acc = 0.0f;
    #pragma unroll 16
    for (int k = 0; k < 128; k++) acc = fmaf(ms[k], Wm[k * D + t], acc);
    g_tg[b * D + t] = ftanh(acc);
}

// ---------------------------------------------------------------------------
// K3: coefs = sigmoid(<x2, tg[batch]>); out = segment_sum(coef * x2).
// fp16 x2, 4 rows pipelined, uniform fast path.
// ---------------------------------------------------------------------------
__global__ void __launch_bounds__(256) k_out(
    const int* __restrict__ bw, float* __restrict__ out, int N, int rpw)
{
    int tid = threadIdx.x, lane = tid & 31;
    int warp = blockIdx.x * (blockDim.x >> 5) + (tid >> 5);
    long long r0l = (long long)warp * rpw;
    if (r0l >= N) return;
    int rs = (int)r0l;
    int re = min(N, rs + rpw);

    bool is64 = (g_is64 != 0);
    float4 acc = make_float4(0.f, 0.f, 0.f, 0.f);
    float4 tgv = make_float4(0.f, 0.f, 0.f, 0.f);
    int cur_b = -1;

    for (int r0 = rs; r0 < re; r0 += 4) {
        int m = min(4, re - r0);
        float4 xv[4]; int bb[4];
        #pragma unroll
        for (int q = 0; q < 4; q++) {
            int rr = r0 + q; if (rr >= re) rr = re - 1;
            bb[q] = is64 ? bw[2 * rr] : bw[rr];
            float2 u = __ldcs((const float2*)&g_x2h[(size_t)rr * D + lane * 4]);
            unsigned u0 = __float_as_uint(u.x), u1 = __float_as_uint(u.y);
            float2 f0 = __half22float2(*(__half2*)&u0);
            float2 f1 = __half22float2(*(__half2*)&u1);
            xv[q] = make_float4(f0.x, f0.y, f1.x, f1.y);
        }

        bool uni = (m == 4) & (bb[0] == cur_b) & (bb[1] == cur_b) &
                   (bb[2] == cur_b) & (bb[3] == cur_b);
        if (uni) {
            float s[4];
            #pragma unroll
            for (int q = 0; q < 4; q++)
                s[q] = fmaf(xv[q].x, tgv.x, fmaf(xv[q].y, tgv.y,
                       fmaf(xv[q].z, tgv.z, xv[q].w * tgv.w)));
            #pragma unroll
            for (int off = 16; off >= 1; off >>= 1) {
                #pragma unroll
                for (int q = 0; q < 4; q++)
                    s[q] += __shfl_xor_sync(0xffffffffu, s[q], off);
            }
            #pragma unroll
            for (int q = 0; q < 4; q++) {
                float coef = fsigmoid(s[q]);
                acc.x = fmaf(coef, xv[q].x, acc.x);
                acc.y = fmaf(coef, xv[q].y, acc.y);
                acc.z = fmaf(coef, xv[q].z, acc.z);
                acc.w = fmaf(coef, xv[q].w, acc.w);
            }
        } else {
            #pragma unroll
            for (int q = 0; q < 4; q++) {
                if (q >= m) break;
                int b = bb[q];
                if (b != cur_b) {
                    if (cur_b >= 0) {
                        float* dst = &out[cur_b * D + lane * 4];
                        atomicAdd(dst + 0, acc.x);
                        atomicAdd(dst + 1, acc.y);
                        atomicAdd(dst + 2, acc.z);
                        atomicAdd(dst + 3, acc.w);
                    }
                    acc = make_float4(0.f, 0.f, 0.f, 0.f);
                    cur_b = b;
                    tgv = ((const float4*)g_tg)[b * 32 + lane];
                }
                float s = fmaf(xv[q].x, tgv.x, fmaf(xv[q].y, tgv.y,
                          fmaf(xv[q].z, tgv.z, xv[q].w * tgv.w)));
                #pragma unroll
                for (int off = 16; off >= 1; off >>= 1)
                    s += __shfl_xor_sync(0xffffffffu, s, off);
                float coef = fsigmoid(s);
                acc.x = fmaf(coef, xv[q].x, acc.x);
                acc.y = fmaf(coef, xv[q].y, acc.y);
                acc.z = fmaf(coef, xv[q].z, acc.z);
                acc.w = fmaf(coef, xv[q].w, acc.w);
            }
        }
    }
    if (cur_b >= 0) {
        float* dst = &out[cur_b * D + lane * 4];
        atomicAdd(dst + 0, acc.x);
        atomicAdd(dst + 1, acc.y);
        atomicAdd(dst + 2, acc.z);
        atomicAdd(dst + 3, acc.w);
    }
}

// ---------------------------------------------------------------------------
// Inputs (metadata order): x, batch, [size], Wm, fc1_w, fc1_b, fc2_w, fc2_b
// ---------------------------------------------------------------------------
extern "C" void kernel_launch(void* const* d_in, const int* in_sizes, int n_in,
                              void* d_out, int out_size)
{
    const float* x  = (const float*)d_in[0];
    const int*   bw = (const int*)d_in[1];
    int base = 2;
    if (n_in >= 8 && in_sizes[2] < 64) base = 3;   // scalar 'size' input present
    const float* Wm   = (const float*)d_in[base + 0];
    const float* fc1w = (const float*)d_in[base + 1];
    const float* fc1b = (const float*)d_in[base + 2];
    const float* fc2w = (const float*)d_in[base + 3];
    const float* fc2b = (const float*)d_in[base + 4];

    int N = in_sizes[0] / D;
    if (N > NMAX) N = NMAX;
    int B = out_size / D;
    if (B > BMAX) B = BMAX;
    float* out = (float*)d_out;

    k_init<<<256, 256>>>(out, out_size, B, bw, N);

    // k_mlp: 8 warps/block, 16-row HMMA groups. smem = 16KB frags + 66KB x-stage
    const size_t MSMEM = 2048 * sizeof(uint2)
                       + (size_t)8 * 16 * XS_STRIDE * sizeof(float);   // 83968 B
    static int attr_done = 0;
    if (!attr_done) {
        cudaFuncSetAttribute(k_mlp, cudaFuncAttributeMaxDynamicSharedMemorySize,
                             (int)MSMEM);
        attr_done = 1;
    }
    const int RPW = 224;                           // multiple of 16; ~1 wave
    int warps = (N + RPW - 1) / RPW;
    int mblocks = (warps + 7) / 8;
    k_mlp<<<mblocks, 256, MSMEM>>>(x, bw, fc1w, fc1b, fc2w, fc2b, N, RPW);

    k_global<<<B, 128>>>(Wm, B);

    const int RPW_OUT = 48;
    int owarps = (N + RPW_OUT - 1) / RPW_OUT;
    int oblocks = (owarps + 7) / 8;
    k_out<<<oblocks, 256>>>(bw, out, N, RPW_OUT);
}

// round 9
// speedup vs baseline: 7.4385x; 1.0960x over previous
#include <cuda_runtime.h>
#include <cuda_fp16.h>

#define D 128
#define NMAX 500000
#define BMAX 4096
#define XS_STRIDE 132   // padded floats per staged row (bank spread)

// Scratch (static __device__ globals — no allocation anywhere)
__device__ __align__(16) __half g_x2h[(size_t)NMAX * D];  // 128 MB fp16 x2
__device__ float g_sums[BMAX * D];
__device__ float g_cnt[BMAX];
__device__ float g_tg[BMAX * D];
__device__ int   g_is64;

__device__ __forceinline__ float ftanh(float v) {
    float r;
    asm("tanh.approx.f32 %0,%1;" : "=f"(r) : "f"(v));
    return r;
}
__device__ __forceinline__ float fsigmoid(float v) {
    float r;
    asm("tanh.approx.f32 %0,%1;" : "=f"(r) : "f"(0.5f * v));
    return fmaf(0.5f, r, 0.5f);
}

__device__ __forceinline__ void cpa16(const void* smem_dst, const void* gmem_src) {
    unsigned s = (unsigned)__cvta_generic_to_shared(smem_dst);
    asm volatile("cp.async.cg.shared.global [%0],[%1],16;" :: "r"(s), "l"(gmem_src));
}
#define CP_COMMIT() asm volatile("cp.async.commit_group;")
#define CP_WAIT1()  asm volatile("cp.async.wait_group 1;")
#define CP_WAIT0()  asm volatile("cp.async.wait_group 0;")

// m16n8k16 row.col f32 += f16*f16
__device__ __forceinline__ void mma16816(float c[4], const unsigned a[4], const unsigned b[2]) {
    asm volatile(
        "mma.sync.aligned.m16n8k16.row.col.f32.f16.f16.f32 "
        "{%0,%1,%2,%3},{%4,%5,%6,%7},{%8,%9},{%0,%1,%2,%3};"
        : "+f"(c[0]), "+f"(c[1]), "+f"(c[2]), "+f"(c[3])
        : "r"(a[0]), "r"(a[1]), "r"(a[2]), "r"(a[3]), "r"(b[0]), "r"(b[1]));
}

__device__ __forceinline__ unsigned packh2(float a, float b) {
    __half2 h = __floats2half2_rn(a, b);
    return *(unsigned*)&h;
}

// ---------------------------------------------------------------------------
// K0: zero accumulators + output; detect batch element width (int64 vs int32).
// ---------------------------------------------------------------------------
__global__ void k_init(float* out, int outn, int B, const int* bw, int N) {
    int i = blockIdx.x * blockDim.x + threadIdx.x;
    int stride = gridDim.x * blockDim.x;
    for (int k = i; k < B * D; k += stride) g_sums[k] = 0.0f;
    for (int k = i; k < B; k += stride) g_cnt[k] = 0.0f;
    for (int k = i; k < outn; k += stride) out[k] = 0.0f;
    if (i == 0) {
        int io = N - 1;
        if (!(io & 1)) io--;
        g_is64 = (io >= 1 && bw[io] == 0) ? 1 : 0;
    }
}

// ---------------------------------------------------------------------------
// K1: fused MLP + x2 + sorted-segment partial sums via HMMA m16n8k16.
// 16 rows per warp group, DOUBLE-BUFFERED cp.async x staging (latency hidden
// behind previous group's compute). fc1 C-frags map directly to fc2 A-frags.
// 5 warps/block, 2 blocks/SM (smem 100.8KB).
// ---------------------------------------------------------------------------
__global__ void __launch_bounds__(160, 2) k_mlp(
    const float* __restrict__ x, const int* __restrict__ bw,
    const float* __restrict__ fc1w, const float* __restrict__ fc1b,
    const float* __restrict__ fc2w, const float* __restrict__ fc2b,
    int N, int rpw)
{
    extern __shared__ char sm_[];
    uint2* w1f = (uint2*)sm_;                 // 1024 frags: [kt*4+nt][lane]
    uint2* w2f = w1f + 1024;                  // 1024 frags: [kt2*16+nt][lane]
    float* xs_all = (float*)(w2f + 1024);     // 5 warps * 2 bufs * 16 * 132 floats

    int tid = threadIdx.x;
    // Build weight fragments (B-frag layout, col-major B = W[n][k])
    for (int e = tid; e < 1024; e += 160) {
        int tile = e >> 5, ln = e & 31;
        int gg = ln >> 2, mm = ln & 3;
        {   // fc1: tile = kt*4 + nt
            int kt = tile >> 2, nt = tile & 3;
            const float* wr = fc1w + (nt * 8 + gg) * 128 + kt * 16 + 2 * mm;
            w1f[e] = make_uint2(packh2(wr[0], wr[1]), packh2(wr[8], wr[9]));
        }
        {   // fc2: tile = kt2*16 + nt
            int kt2 = tile >> 4, nt = tile & 15;
            const float* wr = fc2w + (nt * 8 + gg) * 32 + kt2 * 16 + 2 * mm;
            w2f[e] = make_uint2(packh2(wr[0], wr[1]), packh2(wr[8], wr[9]));
        }
    }
    __syncthreads();

    int lane = tid & 31, wid = tid >> 5;
    int g = lane >> 2, m = lane & 3;
    const int BUFSZ = 16 * XS_STRIDE;
    float* xsb = xs_all + wid * (2 * BUFSZ);

    int warp = blockIdx.x * 5 + wid;
    long long r0l = (long long)warp * rpw;
    if (r0l >= N) return;
    int rs = (int)r0l;
    int re = min(N, rs + rpw);

    bool is64 = (g_is64 != 0);
    float b1v[8];
    #pragma unroll
    for (int nt = 0; nt < 4; nt++) {
        float2 t = *(const float2*)&fc1b[nt * 8 + 2 * m];
        b1v[nt * 2] = t.x; b1v[nt * 2 + 1] = t.y;
    }

    float sacc[32];
    #pragma unroll
    for (int i = 0; i < 32; i++) sacc[i] = 0.0f;
    int cur_b = -1, cnt = 0;

    // prologue: group 0 -> buf 0
    #pragma unroll
    for (int q = 0; q < 16; q++) {
        int rr = rs + q; if (rr >= re) rr = re - 1;
        cpa16(&xsb[q * XS_STRIDE + lane * 4], &x[(size_t)rr * D + lane * 4]);
    }
    CP_COMMIT();

    int buf = 0;
    for (int r0 = rs; r0 < re; r0 += 16) {
        // issue next group into other buffer, then wait for current
        if (r0 + 16 < re) {
            float* nb = xsb + (buf ^ 1) * BUFSZ;
            #pragma unroll
            for (int q = 0; q < 16; q++) {
                int rr = r0 + 16 + q; if (rr >= re) rr = re - 1;
                cpa16(&nb[q * XS_STRIDE + lane * 4], &x[(size_t)rr * D + lane * 4]);
            }
            CP_COMMIT();
            CP_WAIT1();
        } else {
            CP_WAIT0();
        }
        __syncwarp();
        const float* xs = xsb + buf * BUFSZ;
        buf ^= 1;

        // batch ids (lanes 0..15 hold row lane's id)
        int mybat = 0;
        if (lane < 16) {
            int rr = r0 + lane; if (rr >= re) rr = re - 1;
            mybat = is64 ? bw[2 * rr] : bw[rr];
        }
        int nvalid = min(16, re - r0);
        int b_first = __shfl_sync(0xffffffffu, mybat, 0);
        int b_last  = __shfl_sync(0xffffffffu, mybat, nvalid - 1);
        bool mixed = (b_first != b_last);     // sorted => ends equal <=> uniform

        if ((mixed || b_first != cur_b) && cnt > 0) {
            #pragma unroll
            for (int i = 0; i < 32; i++) {
                sacc[i] += __shfl_xor_sync(0xffffffffu, sacc[i], 4);
                sacc[i] += __shfl_xor_sync(0xffffffffu, sacc[i], 8);
                sacc[i] += __shfl_xor_sync(0xffffffffu, sacc[i], 16);
            }
            if (lane < 4) {
                #pragma unroll
                for (int nt = 0; nt < 16; nt++) {
                    atomicAdd(&g_sums[cur_b * D + nt * 8 + 2 * lane],     sacc[nt * 2]);
                    atomicAdd(&g_sums[cur_b * D + nt * 8 + 2 * lane + 1], sacc[nt * 2 + 1]);
                }
            }
            if (lane == 0) atomicAdd(&g_cnt[cur_b], (float)cnt);
            #pragma unroll
            for (int i = 0; i < 32; i++) sacc[i] = 0.0f;
            cnt = 0;
        }
        if (!mixed) { cur_b = b_first; cnt += nvalid; }
        else        { cur_b = -1; }

        // --- fc1: C1[nt] = X @ W1^T (tile nt) ---
        float C1[4][4];
        #pragma unroll
        for (int nt = 0; nt < 4; nt++)
            #pragma unroll
            for (int i = 0; i < 4; i++) C1[nt][i] = 0.0f;

        #pragma unroll
        for (int kt = 0; kt < 8; kt++) {
            const float* xb = xs + kt * 16 + 2 * m;
            float2 p0 = *(const float2*)&xb[g * XS_STRIDE];
            float2 p1 = *(const float2*)&xb[(g + 8) * XS_STRIDE];
            float2 p2 = *(const float2*)&xb[g * XS_STRIDE + 8];
            float2 p3 = *(const float2*)&xb[(g + 8) * XS_STRIDE + 8];
            unsigned A[4];
            A[0] = packh2(p0.x, p0.y);
            A[1] = packh2(p1.x, p1.y);
            A[2] = packh2(p2.x, p2.y);
            A[3] = packh2(p3.x, p3.y);
            #pragma unroll
            for (int nt = 0; nt < 4; nt++) {
                uint2 bf = w1f[(kt * 4 + nt) * 32 + lane];
                unsigned B[2] = { bf.x, bf.y };
                mma16816(C1[nt], A, B);
            }
        }

        // --- bias + ReLU + direct C->A repack for fc2 ---
        unsigned A2[2][4];
        #pragma unroll
        for (int kt2 = 0; kt2 < 2; kt2++) {
            int nta = 2 * kt2, ntb = 2 * kt2 + 1;
            float ha0 = fmaxf(C1[nta][0] + b1v[nta * 2],     0.0f);
            float ha1 = fmaxf(C1[nta][1] + b1v[nta * 2 + 1], 0.0f);
            float ha2 = fmaxf(C1[nta][2] + b1v[nta * 2],     0.0f);
            float ha3 = fmaxf(C1[nta][3] + b1v[nta * 2 + 1], 0.0f);
            float hb0 = fmaxf(C1[ntb][0] + b1v[ntb * 2],     0.0f);
            float hb1 = fmaxf(C1[ntb][1] + b1v[ntb * 2 + 1], 0.0f);
            float hb2 = fmaxf(C1[ntb][2] + b1v[ntb * 2],     0.0f);
            float hb3 = fmaxf(C1[ntb][3] + b1v[ntb * 2 + 1], 0.0f);
            A2[kt2][0] = packh2(ha0, ha1);
            A2[kt2][1] = packh2(ha2, ha3);
            A2[kt2][2] = packh2(hb0, hb1);
            A2[kt2][3] = packh2(hb2, hb3);
        }

        // --- fc2 (two halves of 8 n-tiles) + epilogue ---
        bool vg  = (r0 + g)     < re;
        bool vg8 = (r0 + g + 8) < re;
        int bg = 0, bg8 = 0;
        if (mixed) {
            bg  = __shfl_sync(0xffffffffu, mybat, g);
            bg8 = __shfl_sync(0xffffffffu, mybat, g + 8);
        }

        #pragma unroll
        for (int hf = 0; hf < 2; hf++) {
            float C2[8][4];
            #pragma unroll
            for (int nn = 0; nn < 8; nn++) {
                int nt = hf * 8 + nn;
                float2 b2 = *(const float2*)&fc2b[nt * 8 + 2 * m];
                C2[nn][0] = b2.x; C2[nn][1] = b2.y;
                C2[nn][2] = b2.x; C2[nn][3] = b2.y;
                #pragma unroll
                for (int kt2 = 0; kt2 < 2; kt2++) {
                    uint2 bf = w2f[(kt2 * 16 + nt) * 32 + lane];
                    unsigned B[2] = { bf.x, bf.y };
                    mma16816(C2[nn], A2[kt2], B);
                }
            }
            #pragma unroll
            for (int nn = 0; nn < 8; nn++) {
                int nt = hf * 8 + nn;
                int dim = nt * 8 + 2 * m;
                float a0 = ftanh(C2[nn][0]), a1 = ftanh(C2[nn][1]);
                float a2 = ftanh(C2[nn][2]), a3 = ftanh(C2[nn][3]);
                float2 xg  = *(const float2*)&xs[g * XS_STRIDE + dim];
                float2 xg8 = *(const float2*)&xs[(g + 8) * XS_STRIDE + dim];
                float v0 = fmaf(a0, xg.x,  xg.x);
                float v1 = fmaf(a1, xg.y,  xg.y);
                float v2 = fmaf(a2, xg8.x, xg8.x);
                float v3 = fmaf(a3, xg8.y, xg8.y);
                if (vg) {
                    __half2 hh = __floats2half2_rn(v0, v1);
                    *(__half2*)&g_x2h[(size_t)(r0 + g) * D + dim] = hh;
                }
                if (vg8) {
                    __half2 hh = __floats2half2_rn(v2, v3);
                    *(__half2*)&g_x2h[(size_t)(r0 + g + 8) * D + dim] = hh;
                }
                if (!mixed) {
                    sacc[nt * 2]     += (vg ? v0 : 0.0f) + (vg8 ? v2 : 0.0f);
                    sacc[nt * 2 + 1] += (vg ? v1 : 0.0f) + (vg8 ? v3 : 0.0f);
                } else {
                    if (vg) {
                        atomicAdd(&g_sums[bg * D + dim],     v0);
                        atomicAdd(&g_sums[bg * D + dim + 1], v1);
                    }
                    if (vg8) {
                        atomicAdd(&g_sums[bg8 * D + dim],     v2);
                        atomicAdd(&g_sums[bg8 * D + dim + 1], v3);
                    }
                }
            }
        }
        if (mixed && lane < nvalid) atomicAdd(&g_cnt[mybat], 1.0f);
    }

    // final flush
    if (cnt > 0) {
        #pragma unroll
        for (int i = 0; i < 32; i++) {
            sacc[i] += __shfl_xor_sync(0xffffffffu, sacc[i], 4);
            sacc[i] += __shfl_xor_sync(0xffffffffu, sacc[i], 8);
            sacc[i] += __shfl_xor_sync(0xffffffffu, sacc[i], 16);
        }
        if (lane < 4) {
            #pragma unroll
            for (int nt = 0; nt < 16; nt++) {
                atomicAdd(&g_sums[cur_b * D + nt * 8 + 2 * lane],     sacc[nt * 2]);
                atomicAdd(&g_sums[cur_b * D + nt * 8 + 2 * lane + 1], sacc[nt * 2 + 1]);
            }
        }
        if (lane == 0) atomicAdd(&g_cnt[cur_b], (float)cnt);
    }
}

// ---------------------------------------------------------------------------
// K2: tg[b] = tanh( (sums[b]/max(cnt,1)) @ Wm ).  One block per segment.
// ---------------------------------------------------------------------------
__global__ void k_global(const float* __restrict__ Wm, int B) {
    int b = blockIdx.x, t = threadIdx.x;
    __shared__ float ms[128];
    float c = fmaxf(g_cnt[b], 1.0f);
    ms[t] = g_sums[b * D + t] / c;
    __syncthreads();
    float acc = 0.0f;
    #pragma unroll 16
    for (int k = 0; k < 128; k++) acc = fmaf(ms[k], Wm[k * D + t], acc);
    g_tg[b * D + t] = ftanh(acc);
}

// ---------------------------------------------------------------------------
// K3: coefs = sigmoid(<x2, tg[batch]>); out = segment_sum(coef * x2).
// 16 lanes per row, 8 dims per lane (LDG.128), 4-step half-warp reduce,
// 2 rows x 2 pairs per iteration.
// ---------------------------------------------------------------------------
__global__ void __launch_bounds__(256) k_out(
    const int* __restrict__ bw, float* __restrict__ out, int N, int rpw)
{
    int tid = threadIdx.x, lane = tid & 31;
    int half = lane >> 4, hl = lane & 15;
    int warp = blockIdx.x * (blockDim.x >> 5) + (tid >> 5);
    long long r0l = (long long)warp * rpw;
    if (r0l >= N) return;
    int rs = (int)r0l;
    int re = min(N, rs + rpw);

    bool is64 = (g_is64 != 0);
    float acc[8], tg0[8];
    #pragma unroll
    for (int i = 0; i < 8; i++) { acc[i] = 0.0f; tg0[i] = 0.0f; }
    int cur_b = -1;

    for (int r0 = rs; r0 < re; r0 += 4) {
        #pragma unroll
        for (int p = 0; p < 2; p++) {
            int r = r0 + 2 * p + half;
            bool valid = (r < re);
            int rr = valid ? r : re - 1;
            int b = is64 ? bw[2 * rr] : bw[rr];

            if (__any_sync(0xffffffffu, b != cur_b)) {
                if (b != cur_b) {
                    if (cur_b >= 0) {
                        #pragma unroll
                        for (int i = 0; i < 8; i++)
                            atomicAdd(&out[cur_b * D + hl * 8 + i], acc[i]);
                        #pragma unroll
                        for (int i = 0; i < 8; i++) acc[i] = 0.0f;
                    }
                    cur_b = b;
                    float4 t0 = *(const float4*)&g_tg[b * D + hl * 8];
                    float4 t1 = *(const float4*)&g_tg[b * D + hl * 8 + 4];
                    tg0[0] = t0.x; tg0[1] = t0.y; tg0[2] = t0.z; tg0[3] = t0.w;
                    tg0[4] = t1.x; tg0[5] = t1.y; tg0[6] = t1.z; tg0[7] = t1.w;
                }
            }

            float4 u = __ldcs((const float4*)&g_x2h[(size_t)rr * D + hl * 8]);
            unsigned w0 = __float_as_uint(u.x), w1 = __float_as_uint(u.y);
            unsigned w2 = __float_as_uint(u.z), w3 = __float_as_uint(u.w);
            float2 f0 = __half22float2(*(__half2*)&w0);
            float2 f1 = __half22float2(*(__half2*)&w1);
            float2 f2 = __half22float2(*(__half2*)&w2);
            float2 f3 = __half22float2(*(__half2*)&w3);
            float xv[8] = { f0.x, f0.y, f1.x, f1.y, f2.x, f2.y, f3.x, f3.y };

            float s = xv[0] * tg0[0];
            #pragma unroll
            for (int i = 1; i < 8; i++) s = fmaf(xv[i], tg0[i], s);
            s += __shfl_xor_sync(0xffffffffu, s, 1);
            s += __shfl_xor_sync(0xffffffffu, s, 2);
            s += __shfl_xor_sync(0xffffffffu, s, 4);
            s += __shfl_xor_sync(0xffffffffu, s, 8);
            float coef = fsigmoid(s);
            if (valid) {
                #pragma unroll
                for (int i = 0; i < 8; i++) acc[i] = fmaf(coef, xv[i], acc[i]);
            }
        }
    }
    if (cur_b >= 0) {
        #pragma unroll
        for (int i = 0; i < 8; i++)
            atomicAdd(&out[cur_b * D + hl * 8 + i], acc[i]);
    }
}

// ---------------------------------------------------------------------------
// Inputs (metadata order): x, batch, [size], Wm, fc1_w, fc1_b, fc2_w, fc2_b
// ---------------------------------------------------------------------------
extern "C" void kernel_launch(void* const* d_in, const int* in_sizes, int n_in,
                              void* d_out, int out_size)
{
    const float* x  = (const float*)d_in[0];
    const int*   bw = (const int*)d_in[1];
    int base = 2;
    if (n_in >= 8 && in_sizes[2] < 64) base = 3;   // scalar 'size' input present
    const float* Wm   = (const float*)d_in[base + 0];
    const float* fc1w = (const float*)d_in[base + 1];
    const float* fc1b = (const float*)d_in[base + 2];
    const float* fc2w = (const float*)d_in[base + 3];
    const float* fc2b = (const float*)d_in[base + 4];

    int N = in_sizes[0] / D;
    if (N > NMAX) N = NMAX;
    int B = out_size / D;
    if (B > BMAX) B = BMAX;
    float* out = (float*)d_out;

    k_init<<<256, 256>>>(out, out_size, B, bw, N);

    // k_mlp: 5 warps/block, 16-row HMMA groups, double-buffered cp.async.
    // smem = 16KB frags + 5*2*16*132*4B = 100864 B (2 blocks/SM)
    const size_t MSMEM = 2048 * sizeof(uint2)
                       + (size_t)5 * 2 * 16 * XS_STRIDE * sizeof(float);
    static int attr_done = 0;
    if (!attr_done) {
        cudaFuncSetAttribute(k_mlp, cudaFuncAttributeMaxDynamicSharedMemorySize,
                             (int)MSMEM);
        attr_done = 1;
    }
    const int RPW = 352;                           // multiple of 16; ~1 wave
    int warps = (N + RPW - 1) / RPW;
    int mblocks = (warps + 4) / 5;
    k_mlp<<<mblocks, 160, MSMEM>>>(x, bw, fc1w, fc1b, fc2w, fc2b, N, RPW);

    k_global<<<B, 128>>>(Wm, B);

    const int RPW_OUT = 48;
    int owarps = (N + RPW_OUT - 1) / RPW_OUT;
    int oblocks = (owarps + 7) / 8;
    k_out<<<oblocks, 256>>>(bw, out, N, RPW_OUT);
}

// round 10
// speedup vs baseline: 8.1892x; 1.1009x over previous
#include <cuda_runtime.h>
#include <cuda_fp16.h>

#define D 128
#define NMAX 500000
#define BMAX 4096
#define XS_STRIDE 132   // padded floats per staged row (bank spread)

// Scratch (static __device__ globals — no allocation anywhere)
__device__ __align__(16) __half g_x2h[(size_t)NMAX * D];  // 128 MB fp16 x2
__device__ float g_sums[BMAX * D];
__device__ float g_cnt[BMAX];
__device__ float g_tg[BMAX * D];
__device__ int   g_is64;

__device__ __forceinline__ float ftanh(float v) {
    float r;
    asm("tanh.approx.f32 %0,%1;" : "=f"(r) : "f"(v));
    return r;
}
__device__ __forceinline__ float fsigmoid(float v) {
    float r;
    asm("tanh.approx.f32 %0,%1;" : "=f"(r) : "f"(0.5f * v));
    return fmaf(0.5f, r, 0.5f);
}

__device__ __forceinline__ void cpa16(const void* smem_dst, const void* gmem_src) {
    unsigned s = (unsigned)__cvta_generic_to_shared(smem_dst);
    asm volatile("cp.async.cg.shared.global [%0],[%1],16;" :: "r"(s), "l"(gmem_src));
}
#define CP_COMMIT() asm volatile("cp.async.commit_group;")
#define CP_WAIT1()  asm volatile("cp.async.wait_group 1;")
#define CP_WAIT0()  asm volatile("cp.async.wait_group 0;")

// m16n8k16 row.col f32 += f16*f16
__device__ __forceinline__ void mma16816(float c[4], const unsigned a[4], const unsigned b[2]) {
    asm volatile(
        "mma.sync.aligned.m16n8k16.row.col.f32.f16.f16.f32 "
        "{%0,%1,%2,%3},{%4,%5,%6,%7},{%8,%9},{%0,%1,%2,%3};"
        : "+f"(c[0]), "+f"(c[1]), "+f"(c[2]), "+f"(c[3])
        : "r"(a[0]), "r"(a[1]), "r"(a[2]), "r"(a[3]), "r"(b[0]), "r"(b[1]));
}

__device__ __forceinline__ unsigned packh2(float a, float b) {
    __half2 h = __floats2half2_rn(a, b);
    return *(unsigned*)&h;
}

// ---------------------------------------------------------------------------
// K0: zero accumulators + output; detect batch element width (int64 vs int32).
// ---------------------------------------------------------------------------
__global__ void k_init(float* out, int outn, int B, const int* bw, int N) {
    int i = blockIdx.x * blockDim.x + threadIdx.x;
    int stride = gridDim.x * blockDim.x;
    for (int k = i; k < B * D; k += stride) g_sums[k] = 0.0f;
    for (int k = i; k < B; k += stride) g_cnt[k] = 0.0f;
    for (int k = i; k < outn; k += stride) out[k] = 0.0f;
    if (i == 0) {
        int io = N - 1;
        if (!(io & 1)) io--;
        g_is64 = (io >= 1 && bw[io] == 0) ? 1 : 0;
    }
}

// ---------------------------------------------------------------------------
// K1: fused MLP + x2 + sorted-segment partial sums via HMMA m16n8k16.
// 16 rows per warp group, double-buffered cp.async x staging.
// fc1 C-frags map directly to fc2 A-frags. 5 warps/block, 2 blocks/SM.
// ---------------------------------------------------------------------------
__global__ void __launch_bounds__(160, 2) k_mlp(
    const float* __restrict__ x, const int* __restrict__ bw,
    const float* __restrict__ fc1w, const float* __restrict__ fc1b,
    const float* __restrict__ fc2w, const float* __restrict__ fc2b,
    int N, int rpw)
{
    extern __shared__ char sm_[];
    uint2* w1f = (uint2*)sm_;                 // 1024 frags: [kt*4+nt][lane]
    uint2* w2f = w1f + 1024;                  // 1024 frags: [kt2*16+nt][lane]
    float* xs_all = (float*)(w2f + 1024);     // 5 warps * 2 bufs * 16 * 132 floats

    int tid = threadIdx.x;
    // Build weight fragments (B-frag layout, col-major B = W[n][k])
    for (int e = tid; e < 1024; e += 160) {
        int tile = e >> 5, ln = e & 31;
        int gg = ln >> 2, mm = ln & 3;
        {   // fc1: tile = kt*4 + nt
            int kt = tile >> 2, nt = tile & 3;
            const float* wr = fc1w + (nt * 8 + gg) * 128 + kt * 16 + 2 * mm;
            w1f[e] = make_uint2(packh2(wr[0], wr[1]), packh2(wr[8], wr[9]));
        }
        {   // fc2: tile = kt2*16 + nt
            int kt2 = tile >> 4, nt = tile & 15;
            const float* wr = fc2w + (nt * 8 + gg) * 32 + kt2 * 16 + 2 * mm;
            w2f[e] = make_uint2(packh2(wr[0], wr[1]), packh2(wr[8], wr[9]));
        }
    }
    __syncthreads();

    int lane = tid & 31, wid = tid >> 5;
    int g = lane >> 2, m = lane & 3;
    const int BUFSZ = 16 * XS_STRIDE;
    float* xsb = xs_all + wid * (2 * BUFSZ);

    int warp = blockIdx.x * 5 + wid;
    long long r0l = (long long)warp * rpw;
    if (r0l >= N) return;
    int rs = (int)r0l;
    int re = min(N, rs + rpw);

    bool is64 = (g_is64 != 0);
    float b1v[8];
    #pragma unroll
    for (int nt = 0; nt < 4; nt++) {
        float2 t = *(const float2*)&fc1b[nt * 8 + 2 * m];
        b1v[nt * 2] = t.x; b1v[nt * 2 + 1] = t.y;
    }

    float sacc[32];
    #pragma unroll
    for (int i = 0; i < 32; i++) sacc[i] = 0.0f;
    int cur_b = -1, cnt = 0;

    // prologue: group 0 -> buf 0
    #pragma unroll
    for (int q = 0; q < 16; q++) {
        int rr = rs + q; if (rr >= re) rr = re - 1;
        cpa16(&xsb[q * XS_STRIDE + lane * 4], &x[(size_t)rr * D + lane * 4]);
    }
    CP_COMMIT();

    int buf = 0;
    for (int r0 = rs; r0 < re; r0 += 16) {
        // issue next group into other buffer, then wait for current
        if (r0 + 16 < re) {
            float* nb = xsb + (buf ^ 1) * BUFSZ;
            #pragma unroll
            for (int q = 0; q < 16; q++) {
                int rr = r0 + 16 + q; if (rr >= re) rr = re - 1;
                cpa16(&nb[q * XS_STRIDE + lane * 4], &x[(size_t)rr * D + lane * 4]);
            }
            CP_COMMIT();
            CP_WAIT1();
        } else {
            CP_WAIT0();
        }
        __syncwarp();
        const float* xs = xsb + buf * BUFSZ;
        buf ^= 1;

        // batch ids (lanes 0..15 hold row lane's id)
        int mybat = 0;
        if (lane < 16) {
            int rr = r0 + lane; if (rr >= re) rr = re - 1;
            mybat = is64 ? bw[2 * rr] : bw[rr];
        }
        int nvalid = min(16, re - r0);
        int b_first = __shfl_sync(0xffffffffu, mybat, 0);
        int b_last  = __shfl_sync(0xffffffffu, mybat, nvalid - 1);
        bool mixed = (b_first != b_last);     // sorted => ends equal <=> uniform

        if ((mixed || b_first != cur_b) && cnt > 0) {
            #pragma unroll
            for (int i = 0; i < 32; i++) {
                sacc[i] += __shfl_xor_sync(0xffffffffu, sacc[i], 4);
                sacc[i] += __shfl_xor_sync(0xffffffffu, sacc[i], 8);
                sacc[i] += __shfl_xor_sync(0xffffffffu, sacc[i], 16);
            }
            if (lane < 4) {
                #pragma unroll
                for (int nt = 0; nt < 16; nt++) {
                    atomicAdd(&g_sums[cur_b * D + nt * 8 + 2 * lane],     sacc[nt * 2]);
                    atomicAdd(&g_sums[cur_b * D + nt * 8 + 2 * lane + 1], sacc[nt * 2 + 1]);
                }
            }
            if (lane == 0) atomicAdd(&g_cnt[cur_b], (float)cnt);
            #pragma unroll
            for (int i = 0; i < 32; i++) sacc[i] = 0.0f;
            cnt = 0;
        }
        if (!mixed) { cur_b = b_first; cnt += nvalid; }
        else        { cur_b = -1; }

        // --- fc1: C1[nt] = X @ W1^T (tile nt) ---
        float C1[4][4];
        #pragma unroll
        for (int nt = 0; nt < 4; nt++)
            #pragma unroll
            for (int i = 0; i < 4; i++) C1[nt][i] = 0.0f;

        #pragma unroll
        for (int kt = 0; kt < 8; kt++) {
            const float* xb = xs + kt * 16 + 2 * m;
            float2 p0 = *(const float2*)&xb[g * XS_STRIDE];
            float2 p1 = *(const float2*)&xb[(g + 8) * XS_STRIDE];
            float2 p2 = *(const float2*)&xb[g * XS_STRIDE + 8];
            float2 p3 = *(const float2*)&xb[(g + 8) * XS_STRIDE + 8];
            unsigned A[4];
            A[0] = packh2(p0.x, p0.y);
            A[1] = packh2(p1.x, p1.y);
            A[2] = packh2(p2.x, p2.y);
            A[3] = packh2(p3.x, p3.y);
            #pragma unroll
            for (int nt = 0; nt < 4; nt++) {
                uint2 bf = w1f[(kt * 4 + nt) * 32 + lane];
                unsigned B[2] = { bf.x, bf.y };
                mma16816(C1[nt], A, B);
            }
        }

        // --- bias + ReLU + direct C->A repack for fc2 ---
        unsigned A2[2][4];
        #pragma unroll
        for (int kt2 = 0; kt2 < 2; kt2++) {
            int nta = 2 * kt2, ntb = 2 * kt2 + 1;
            float ha0 = fmaxf(C1[nta][0] + b1v[nta * 2],     0.0f);
            float ha1 = fmaxf(C1[nta][1] + b1v[nta * 2 + 1], 0.0f);
            float ha2 = fmaxf(C1[nta][2] + b1v[nta * 2],     0.0f);
            float ha3 = fmaxf(C1[nta][3] + b1v[nta * 2 + 1], 0.0f);
            float hb0 = fmaxf(C1[ntb][0] + b1v[ntb * 2],     0.0f);
            float hb1 = fmaxf(C1[ntb][1] + b1v[ntb * 2 + 1], 0.0f);
            float hb2 = fmaxf(C1[ntb][2] + b1v[ntb * 2],     0.0f);
            float hb3 = fmaxf(C1[ntb][3] + b1v[ntb * 2 + 1], 0.0f);
            A2[kt2][0] = packh2(ha0, ha1);
            A2[kt2][1] = packh2(ha2, ha3);
            A2[kt2][2] = packh2(hb0, hb1);
            A2[kt2][3] = packh2(hb2, hb3);
        }

        // --- fc2 (two halves of 8 n-tiles) + epilogue ---
        bool vg  = (r0 + g)     < re;
        bool vg8 = (r0 + g + 8) < re;
        int bg = 0, bg8 = 0;
        if (mixed) {
            bg  = __shfl_sync(0xffffffffu, mybat, g);
            bg8 = __shfl_sync(0xffffffffu, mybat, g + 8);
        }

        #pragma unroll
        for (int hf = 0; hf < 2; hf++) {
            float C2[8][4];
            #pragma unroll
            for (int nn = 0; nn < 8; nn++) {
                int nt = hf * 8 + nn;
                float2 b2 = *(const float2*)&fc2b[nt * 8 + 2 * m];
                C2[nn][0] = b2.x; C2[nn][1] = b2.y;
                C2[nn][2] = b2.x; C2[nn][3] = b2.y;
                #pragma unroll
                for (int kt2 = 0; kt2 < 2; kt2++) {
                    uint2 bf = w2f[(kt2 * 16 + nt) * 32 + lane];
                    unsigned B[2] = { bf.x, bf.y };
                    mma16816(C2[nn], A2[kt2], B);
                }
            }
            #pragma unroll
            for (int nn = 0; nn < 8; nn++) {
                int nt = hf * 8 + nn;
                int dim = nt * 8 + 2 * m;
                float a0 = ftanh(C2[nn][0]), a1 = ftanh(C2[nn][1]);
                float a2 = ftanh(C2[nn][2]), a3 = ftanh(C2[nn][3]);
                float2 xg  = *(const float2*)&xs[g * XS_STRIDE + dim];
                float2 xg8 = *(const float2*)&xs[(g + 8) * XS_STRIDE + dim];
                float v0 = fmaf(a0, xg.x,  xg.x);
                float v1 = fmaf(a1, xg.y,  xg.y);
                float v2 = fmaf(a2, xg8.x, xg8.x);
                float v3 = fmaf(a3, xg8.y, xg8.y);
                if (vg) {
                    __half2 hh = __floats2half2_rn(v0, v1);
                    *(__half2*)&g_x2h[(size_t)(r0 + g) * D + dim] = hh;
                }
                if (vg8) {
                    __half2 hh = __floats2half2_rn(v2, v3);
                    *(__half2*)&g_x2h[(size_t)(r0 + g + 8) * D + dim] = hh;
                }
                if (!mixed) {
                    sacc[nt * 2]     += (vg ? v0 : 0.0f) + (vg8 ? v2 : 0.0f);
                    sacc[nt * 2 + 1] += (vg ? v1 : 0.0f) + (vg8 ? v3 : 0.0f);
                } else {
                    if (vg) {
                        atomicAdd(&g_sums[bg * D + dim],     v0);
                        atomicAdd(&g_sums[bg * D + dim + 1], v1);
                    }
                    if (vg8) {
                        atomicAdd(&g_sums[bg8 * D + dim],     v2);
                        atomicAdd(&g_sums[bg8 * D + dim + 1], v3);
                    }
                }
            }
        }
        if (mixed && lane < nvalid) atomicAdd(&g_cnt[mybat], 1.0f);
    }

    // final flush
    if (cnt > 0) {
        #pragma unroll
        for (int i = 0; i < 32; i++) {
            sacc[i] += __shfl_xor_sync(0xffffffffu, sacc[i], 4);
            sacc[i] += __shfl_xor_sync(0xffffffffu, sacc[i], 8);
            sacc[i] += __shfl_xor_sync(0xffffffffu, sacc[i], 16);
        }
        if (lane < 4) {
            #pragma unroll
            for (int nt = 0; nt < 16; nt++) {
                atomicAdd(&g_sums[cur_b * D + nt * 8 + 2 * lane],     sacc[nt * 2]);
                atomicAdd(&g_sums[cur_b * D + nt * 8 + 2 * lane + 1], sacc[nt * 2 + 1]);
            }
        }
        if (lane == 0) atomicAdd(&g_cnt[cur_b], (float)cnt);
    }
}

// ---------------------------------------------------------------------------
// K2: tg[b] = tanh( (sums[b]/max(cnt,1)) @ Wm ).  One block per segment.
// ---------------------------------------------------------------------------
__global__ void k_global(const float* __restrict__ Wm, int B) {
    int b = blockIdx.x, t = threadIdx.x;
    __shared__ float ms[128];
    float c = fmaxf(g_cnt[b], 1.0f);
    ms[t] = g_sums[b * D + t] / c;
    __syncthreads();
    float acc = 0.0f;
    #pragma unroll 16
    for (int k = 0; k < 128; k++) acc = fmaf(ms[k], Wm[k * D + t], acc);
    g_tg[b * D + t] = ftanh(acc);
}

// ---------------------------------------------------------------------------
// K3: coefs = sigmoid(<x2, tg[batch]>); out = segment_sum(coef * x2).
// R8 structure (warp-per-row, uniform fast path) with 8-row groups for
// deeper memory pipelining.
// ---------------------------------------------------------------------------
__global__ void __launch_bounds__(256) k_out(
    const int* __restrict__ bw, float* __restrict__ out, int N, int rpw)
{
    int tid = threadIdx.x, lane = tid & 31;
    int warp = blockIdx.x * (blockDim.x >> 5) + (tid >> 5);
    long long r0l = (long long)warp * rpw;
    if (r0l >= N) return;
    int rs = (int)r0l;
    int re = min(N, rs + rpw);

    bool is64 = (g_is64 != 0);
    float4 acc = make_float4(0.f, 0.f, 0.f, 0.f);
    float4 tgv = make_float4(0.f, 0.f, 0.f, 0.f);
    int cur_b = -1;

    for (int r0 = rs; r0 < re; r0 += 8) {
        int m = min(8, re - r0);
        float4 xv[8]; int bb[8];
        #pragma unroll
        for (int q = 0; q < 8; q++) {
            int rr = r0 + q; if (rr >= re) rr = re - 1;
            bb[q] = is64 ? bw[2 * rr] : bw[rr];
            float2 u = __ldcs((const float2*)&g_x2h[(size_t)rr * D + lane * 4]);
            unsigned u0 = __float_as_uint(u.x), u1 = __float_as_uint(u.y);
            float2 f0 = __half22float2(*(__half2*)&u0);
            float2 f1 = __half22float2(*(__half2*)&u1);
            xv[q] = make_float4(f0.x, f0.y, f1.x, f1.y);
        }

        bool uni = (m == 8) & (bb[0] == cur_b) & (bb[7] == cur_b);
        if (uni) {
            float s[8];
            #pragma unroll
            for (int q = 0; q < 8; q++)
                s[q] = fmaf(xv[q].x, tgv.x, fmaf(xv[q].y, tgv.y,
                       fmaf(xv[q].z, tgv.z, xv[q].w * tgv.w)));
            #pragma unroll
            for (int off = 16; off >= 1; off >>= 1) {
                #pragma unroll
                for (int q = 0; q < 8; q++)
                    s[q] += __shfl_xor_sync(0xffffffffu, s[q], off);
            }
            #pragma unroll
            for (int q = 0; q < 8; q++) {
                float coef = fsigmoid(s[q]);
                acc.x = fmaf(coef, xv[q].x, acc.x);
                acc.y = fmaf(coef, xv[q].y, acc.y);
                acc.z = fmaf(coef, xv[q].z, acc.z);
                acc.w = fmaf(coef, xv[q].w, acc.w);
            }
        } else {
            #pragma unroll
            for (int q = 0; q < 8; q++) {
                if (q >= m) break;
                int b = bb[q];
                if (b != cur_b) {
                    if (cur_b >= 0) {
                        float* dst = &out[cur_b * D + lane * 4];
                        atomicAdd(dst + 0, acc.x);
                        atomicAdd(dst + 1, acc.y);
                        atomicAdd(dst + 2, acc.z);
                        atomicAdd(dst + 3, acc.w);
                    }
                    acc = make_float4(0.f, 0.f, 0.f, 0.f);
                    cur_b = b;
                    tgv = ((const float4*)g_tg)[b * 32 + lane];
                }
                float s = fmaf(xv[q].x, tgv.x, fmaf(xv[q].y, tgv.y,
                          fmaf(xv[q].z, tgv.z, xv[q].w * tgv.w)));
                #pragma unroll
                for (int off = 16; off >= 1; off >>= 1)
                    s += __shfl_xor_sync(0xffffffffu, s, off);
                float coef = fsigmoid(s);
                acc.x = fmaf(coef, xv[q].x, acc.x);
                acc.y = fmaf(coef, xv[q].y, acc.y);
                acc.z = fmaf(coef, xv[q].z, acc.z);
                acc.w = fmaf(coef, xv[q].w, acc.w);
            }
        }
    }
    if (cur_b >= 0) {
        float* dst = &out[cur_b * D + lane * 4];
        atomicAdd(dst + 0, acc.x);
        atomicAdd(dst + 1, acc.y);
        atomicAdd(dst + 2, acc.z);
        atomicAdd(dst + 3, acc.w);
    }
}

// ---------------------------------------------------------------------------
// Inputs (metadata order): x, batch, [size], Wm, fc1_w, fc1_b, fc2_w, fc2_b
// ---------------------------------------------------------------------------
extern "C" void kernel_launch(void* const* d_in, const int* in_sizes, int n_in,
                              void* d_out, int out_size)
{
    const float* x  = (const float*)d_in[0];
    const int*   bw = (const int*)d_in[1];
    int base = 2;
    if (n_in >= 8 && in_sizes[2] < 64) base = 3;   // scalar 'size' input present
    const float* Wm   = (const float*)d_in[base + 0];
    const float* fc1w = (const float*)d_in[base + 1];
    const float* fc1b = (const float*)d_in[base + 2];
    const float* fc2w = (const float*)d_in[base + 3];
    const float* fc2b = (const float*)d_in[base + 4];

    int N = in_sizes[0] / D;
    if (N > NMAX) N = NMAX;
    int B = out_size / D;
    if (B > BMAX) B = BMAX;
    float* out = (float*)d_out;

    k_init<<<256, 256>>>(out, out_size, B, bw, N);

    // k_mlp: 5 warps/block, 16-row HMMA groups, double-buffered cp.async.
    // smem = 16KB frags + 5*2*16*132*4B = 100864 B (2 blocks/SM)
    const size_t MSMEM = 2048 * sizeof(uint2)
                       + (size_t)5 * 2 * 16 * XS_STRIDE * sizeof(float);
    static int attr_done = 0;
    if (!attr_done) {
        cudaFuncSetAttribute(k_mlp, cudaFuncAttributeMaxDynamicSharedMemorySize,
                             (int)MSMEM);
        attr_done = 1;
    }
    const int RPW = 344;   // multiple of 8 (16-groups + tail); 291 blocks <= 296 slots
    int warps = (N + RPW - 1) / RPW;
    int mblocks = (warps + 4) / 5;
    k_mlp<<<mblocks, 160, MSMEM>>>(x, bw, fc1w, fc1b, fc2w, fc2b, N, RPW);

    k_global<<<B, 128>>>(Wm, B);

    const int RPW_OUT = 64;
    int owarps = (N + RPW_OUT - 1) / RPW_OUT;
    int oblocks = (owarps + 7) / 8;
    k_out<<<oblocks, 256>>>(bw, out, N, RPW_OUT);
}

// round 11
// speedup vs baseline: 8.8827x; 1.0847x over previous
#include <cuda_runtime.h>
#include <cuda_fp16.h>

#define D 128
#define NMAX 500000
#define BMAX 4096
#define XS_STRIDE 132   // padded floats per staged row (bank spread)
#define X2S_STRIDE 72   // halves per staged x2 row (144B; 36 words -> conflict-free STS)

// Scratch (static __device__ globals — no allocation anywhere)
__device__ __align__(16) __half g_x2h[(size_t)NMAX * D];  // 128 MB fp16 x2
__device__ float g_sums[BMAX * D];
__device__ float g_cnt[BMAX];
__device__ float g_tg[BMAX * D];
__device__ int   g_is64;

__device__ __forceinline__ float ftanh(float v) {
    float r;
    asm("tanh.approx.f32 %0,%1;" : "=f"(r) : "f"(v));
    return r;
}
__device__ __forceinline__ float fsigmoid(float v) {
    float r;
    asm("tanh.approx.f32 %0,%1;" : "=f"(r) : "f"(0.5f * v));
    return fmaf(0.5f, r, 0.5f);
}

__device__ __forceinline__ void cpa16(const void* smem_dst, const void* gmem_src) {
    unsigned s = (unsigned)__cvta_generic_to_shared(smem_dst);
    asm volatile("cp.async.cg.shared.global [%0],[%1],16;" :: "r"(s), "l"(gmem_src));
}
#define CP_COMMIT() asm volatile("cp.async.commit_group;")
#define CP_WAIT1()  asm volatile("cp.async.wait_group 1;")
#define CP_WAIT0()  asm volatile("cp.async.wait_group 0;")

// m16n8k16 row.col f32 += f16*f16
__device__ __forceinline__ void mma16816(float c[4], const unsigned a[4], const unsigned b[2]) {
    asm volatile(
        "mma.sync.aligned.m16n8k16.row.col.f32.f16.f16.f32 "
        "{%0,%1,%2,%3},{%4,%5,%6,%7},{%8,%9},{%0,%1,%2,%3};"
        : "+f"(c[0]), "+f"(c[1]), "+f"(c[2]), "+f"(c[3])
        : "r"(a[0]), "r"(a[1]), "r"(a[2]), "r"(a[3]), "r"(b[0]), "r"(b[1]));
}

__device__ __forceinline__ unsigned packh2(float a, float b) {
    __half2 h = __floats2half2_rn(a, b);
    return *(unsigned*)&h;
}

// ---------------------------------------------------------------------------
// K0: zero accumulators + output; detect batch element width (int64 vs int32).
// ---------------------------------------------------------------------------
__global__ void k_init(float* out, int outn, int B, const int* bw, int N) {
    int i = blockIdx.x * blockDim.x + threadIdx.x;
    int stride = gridDim.x * blockDim.x;
    for (int k = i; k < B * D; k += stride) g_sums[k] = 0.0f;
    for (int k = i; k < B; k += stride) g_cnt[k] = 0.0f;
    for (int k = i; k < outn; k += stride) out[k] = 0.0f;
    if (i == 0) {
        int io = N - 1;
        if (!(io & 1)) io--;
        g_is64 = (io >= 1 && bw[io] == 0) ? 1 : 0;
    }
}

// ---------------------------------------------------------------------------
// K1: fused MLP + x2 + sorted-segment partial sums via HMMA m16n8k16.
// 16 rows per warp group, double-buffered cp.async x staging.
// fc1 C-frags map directly to fc2 A-frags. x2 stores go through a small
// conflict-free fp16 smem transpose tile -> coalesced STG.128 (the direct
// per-fragment STG.32 pattern scattered 8 gmem rows per instruction).
// 5 warps/block, 2 blocks/SM (smem 109.8KB).
// ---------------------------------------------------------------------------
__global__ void __launch_bounds__(160, 2) k_mlp(
    const float* __restrict__ x, const int* __restrict__ bw,
    const float* __restrict__ fc1w, const float* __restrict__ fc1b,
    const float* __restrict__ fc2w, const float* __restrict__ fc2b,
    int N, int rpw)
{
    extern __shared__ char sm_[];
    uint2* w1f = (uint2*)sm_;                 // 1024 frags: [kt*4+nt][lane]
    uint2* w2f = w1f + 1024;                  // 1024 frags: [kt2*16+nt][lane]
    float* xs_all = (float*)(w2f + 1024);     // 5 warps * 2 bufs * 16 * 132 floats
    __half* x2s_all = (__half*)(xs_all + 5 * 2 * 16 * XS_STRIDE);  // 5 * 16 * 72 halves

    int tid = threadIdx.x;
    // Build weight fragments (B-frag layout, col-major B = W[n][k])
    for (int e = tid; e < 1024; e += 160) {
        int tile = e >> 5, ln = e & 31;
        int gg = ln >> 2, mm = ln & 3;
        {   // fc1: tile = kt*4 + nt
            int kt = tile >> 2, nt = tile & 3;
            const float* wr = fc1w + (nt * 8 + gg) * 128 + kt * 16 + 2 * mm;
            w1f[e] = make_uint2(packh2(wr[0], wr[1]), packh2(wr[8], wr[9]));
        }
        {   // fc2: tile = kt2*16 + nt
            int kt2 = tile >> 4, nt = tile & 15;
            const float* wr = fc2w + (nt * 8 + gg) * 32 + kt2 * 16 + 2 * mm;
            w2f[e] = make_uint2(packh2(wr[0], wr[1]), packh2(wr[8], wr[9]));
        }
    }
    __syncthreads();

    int lane = tid & 31, wid = tid >> 5;
    int g = lane >> 2, m = lane & 3;
    const int BUFSZ = 16 * XS_STRIDE;
    float* xsb = xs_all + wid * (2 * BUFSZ);
    __half* x2w = x2s_all + wid * (16 * X2S_STRIDE);

    int warp = blockIdx.x * 5 + wid;
    long long r0l = (long long)warp * rpw;
    if (r0l >= N) return;
    int rs = (int)r0l;
    int re = min(N, rs + rpw);

    bool is64 = (g_is64 != 0);
    float b1v[8];
    #pragma unroll
    for (int nt = 0; nt < 4; nt++) {
        float2 t = *(const float2*)&fc1b[nt * 8 + 2 * m];
        b1v[nt * 2] = t.x; b1v[nt * 2 + 1] = t.y;
    }

    float sacc[32];
    #pragma unroll
    for (int i = 0; i < 32; i++) sacc[i] = 0.0f;
    int cur_b = -1, cnt = 0;

    // prologue: group 0 -> buf 0
    #pragma unroll
    for (int q = 0; q < 16; q++) {
        int rr = rs + q; if (rr >= re) rr = re - 1;
        cpa16(&xsb[q * XS_STRIDE + lane * 4], &x[(size_t)rr * D + lane * 4]);
    }
    CP_COMMIT();

    int buf = 0;
    for (int r0 = rs; r0 < re; r0 += 16) {
        // issue next group into other buffer, then wait for current
        if (r0 + 16 < re) {
            float* nb = xsb + (buf ^ 1) * BUFSZ;
            #pragma unroll
            for (int q = 0; q < 16; q++) {
                int rr = r0 + 16 + q; if (rr >= re) rr = re - 1;
                cpa16(&nb[q * XS_STRIDE + lane * 4], &x[(size_t)rr * D + lane * 4]);
            }
            CP_COMMIT();
            CP_WAIT1();
        } else {
            CP_WAIT0();
        }
        __syncwarp();
        const float* xs = xsb + buf * BUFSZ;
        buf ^= 1;

        // batch ids (lanes 0..15 hold row lane's id)
        int mybat = 0;
        if (lane < 16) {
            int rr = r0 + lane; if (rr >= re) rr = re - 1;
            mybat = is64 ? bw[2 * rr] : bw[rr];
        }
        int nvalid = min(16, re - r0);
        int b_first = __shfl_sync(0xffffffffu, mybat, 0);
        int b_last  = __shfl_sync(0xffffffffu, mybat, nvalid - 1);
        bool mixed = (b_first != b_last);     // sorted => ends equal <=> uniform

        if ((mixed || b_first != cur_b) && cnt > 0) {
            #pragma unroll
            for (int i = 0; i < 32; i++) {
                sacc[i] += __shfl_xor_sync(0xffffffffu, sacc[i], 4);
                sacc[i] += __shfl_xor_sync(0xffffffffu, sacc[i], 8);
                sacc[i] += __shfl_xor_sync(0xffffffffu, sacc[i], 16);
            }
            if (lane < 4) {
                #pragma unroll
                for (int nt = 0; nt < 16; nt++) {
                    atomicAdd(&g_sums[cur_b * D + nt * 8 + 2 * lane],     sacc[nt * 2]);
                    atomicAdd(&g_sums[cur_b * D + nt * 8 + 2 * lane + 1], sacc[nt * 2 + 1]);
                }
            }
            if (lane == 0) atomicAdd(&g_cnt[cur_b], (float)cnt);
            #pragma unroll
            for (int i = 0; i < 32; i++) sacc[i] = 0.0f;
            cnt = 0;
        }
        if (!mixed) { cur_b = b_first; cnt += nvalid; }
        else        { cur_b = -1; }

        // --- fc1: C1[nt] = X @ W1^T (tile nt) ---
        float C1[4][4];
        #pragma unroll
        for (int nt = 0; nt < 4; nt++)
            #pragma unroll
            for (int i = 0; i < 4; i++) C1[nt][i] = 0.0f;

        #pragma unroll
        for (int kt = 0; kt < 8; kt++) {
            const float* xb = xs + kt * 16 + 2 * m;
            float2 p0 = *(const float2*)&xb[g * XS_STRIDE];
            float2 p1 = *(const float2*)&xb[(g + 8) * XS_STRIDE];
            float2 p2 = *(const float2*)&xb[g * XS_STRIDE + 8];
            float2 p3 = *(const float2*)&xb[(g + 8) * XS_STRIDE + 8];
            unsigned A[4];
            A[0] = packh2(p0.x, p0.y);
            A[1] = packh2(p1.x, p1.y);
            A[2] = packh2(p2.x, p2.y);
            A[3] = packh2(p3.x, p3.y);
            #pragma unroll
            for (int nt = 0; nt < 4; nt++) {
                uint2 bf = w1f[(kt * 4 + nt) * 32 + lane];
                unsigned B[2] = { bf.x, bf.y };
                mma16816(C1[nt], A, B);
            }
        }

        // --- bias + ReLU + direct C->A repack for fc2 ---
        unsigned A2[2][4];
        #pragma unroll
        for (int kt2 = 0; kt2 < 2; kt2++) {
            int nta = 2 * kt2, ntb = 2 * kt2 + 1;
            float ha0 = fmaxf(C1[nta][0] + b1v[nta * 2],     0.0f);
            float ha1 = fmaxf(C1[nta][1] + b1v[nta * 2 + 1], 0.0f);
            float ha2 = fmaxf(C1[nta][2] + b1v[nta * 2],     0.0f);
            float ha3 = fmaxf(C1[nta][3] + b1v[nta * 2 + 1], 0.0f);
            float hb0 = fmaxf(C1[ntb][0] + b1v[ntb * 2],     0.0f);
            float hb1 = fmaxf(C1[ntb][1] + b1v[ntb * 2 + 1], 0.0f);
            float hb2 = fmaxf(C1[ntb][2] + b1v[ntb * 2],     0.0f);
            float hb3 = fmaxf(C1[ntb][3] + b1v[ntb * 2 + 1], 0.0f);
            A2[kt2][0] = packh2(ha0, ha1);
            A2[kt2][1] = packh2(ha2, ha3);
            A2[kt2][2] = packh2(hb0, hb1);
            A2[kt2][3] = packh2(hb2, hb3);
        }

        // --- fc2 (two halves of 8 n-tiles) + epilogue ---
        bool vg  = (r0 + g)     < re;
        bool vg8 = (r0 + g + 8) < re;
        int bg = 0, bg8 = 0;
        if (mixed) {
            bg  = __shfl_sync(0xffffffffu, mybat, g);
            bg8 = __shfl_sync(0xffffffffu, mybat, g + 8);
        }

        #pragma unroll
        for (int hf = 0; hf < 2; hf++) {
            float C2[8][4];
            #pragma unroll
            for (int nn = 0; nn < 8; nn++) {
                int nt = hf * 8 + nn;
                float2 b2 = *(const float2*)&fc2b[nt * 8 + 2 * m];
                C2[nn][0] = b2.x; C2[nn][1] = b2.y;
                C2[nn][2] = b2.x; C2[nn][3] = b2.y;
                #pragma unroll
                for (int kt2 = 0; kt2 < 2; kt2++) {
                    uint2 bf = w2f[(kt2 * 16 + nt) * 32 + lane];
                    unsigned B[2] = { bf.x, bf.y };
                    mma16816(C2[nn], A2[kt2], B);
                }
            }
            #pragma unroll
            for (int nn = 0; nn < 8; nn++) {
                int nt = hf * 8 + nn;
                int dim = nt * 8 + 2 * m;      // global dim
                int ld  = nn * 8 + 2 * m;      // dim within this hf's 64-dim slab
                float a0 = ftanh(C2[nn][0]), a1 = ftanh(C2[nn][1]);
                float a2 = ftanh(C2[nn][2]), a3 = ftanh(C2[nn][3]);
                float2 xg  = *(const float2*)&xs[g * XS_STRIDE + dim];
                float2 xg8 = *(const float2*)&xs[(g + 8) * XS_STRIDE + dim];
                float v0 = fmaf(a0, xg.x,  xg.x);
                float v1 = fmaf(a1, xg.y,  xg.y);
                float v2 = fmaf(a2, xg8.x, xg8.x);
                float v3 = fmaf(a3, xg8.y, xg8.y);
                // conflict-free STS into the transpose tile
                *(__half2*)&x2w[g * X2S_STRIDE + ld]       = __floats2half2_rn(v0, v1);
                *(__half2*)&x2w[(g + 8) * X2S_STRIDE + ld] = __floats2half2_rn(v2, v3);
                if (!mixed) {
                    sacc[nt * 2]     += (vg ? v0 : 0.0f) + (vg8 ? v2 : 0.0f);
                    sacc[nt * 2 + 1] += (vg ? v1 : 0.0f) + (vg8 ? v3 : 0.0f);
                } else {
                    if (vg) {
                        atomicAdd(&g_sums[bg * D + dim],     v0);
                        atomicAdd(&g_sums[bg * D + dim + 1], v1);
                    }
                    if (vg8) {
                        atomicAdd(&g_sums[bg8 * D + dim],     v2);
                        atomicAdd(&g_sums[bg8 * D + dim + 1], v3);
                    }
                }
            }
            __syncwarp();
            // coalesced flush: 4 x STG.128, each 32 lanes x 16B over 4 rows
            #pragma unroll
            for (int it = 0; it < 4; it++) {
                int lrow = it * 4 + (lane >> 3);
                int chunk = lane & 7;
                int rr = r0 + lrow;
                if (rr < re) {
                    float4 v = *(const float4*)&x2w[lrow * X2S_STRIDE + chunk * 8];
                    *(float4*)&g_x2h[(size_t)rr * D + hf * 64 + chunk * 8] = v;
                }
            }
            if (hf == 0) __syncwarp();   // tile reused by hf=1 STS
        }
        if (mixed && lane < nvalid) atomicAdd(&g_cnt[mybat], 1.0f);
    }

    // final flush
    if (cnt > 0) {
        #pragma unroll
        for (int i = 0; i < 32; i++) {
            sacc[i] += __shfl_xor_sync(0xffffffffu, sacc[i], 4);
            sacc[i] += __shfl_xor_sync(0xffffffffu, sacc[i], 8);
            sacc[i] += __shfl_xor_sync(0xffffffffu, sacc[i], 16);
        }
        if (lane < 4) {
            #pragma unroll
            for (int nt = 0; nt < 16; nt++) {
                atomicAdd(&g_sums[cur_b * D + nt * 8 + 2 * lane],     sacc[nt * 2]);
                atomicAdd(&g_sums[cur_b * D + nt * 8 + 2 * lane + 1], sacc[nt * 2 + 1]);
            }
        }
        if (lane == 0) atomicAdd(&g_cnt[cur_b], (float)cnt);
    }
}

// ---------------------------------------------------------------------------
// K2: tg[b] = tanh( (sums[b]/max(cnt,1)) @ Wm ).  One block per segment.
// ---------------------------------------------------------------------------
__global__ void k_global(const float* __restrict__ Wm, int B) {
    int b = blockIdx.x, t = threadIdx.x;
    __shared__ float ms[128];
    float c = fmaxf(g_cnt[b], 1.0f);
    ms[t] = g_sums[b * D + t] / c;
    __syncthreads();
    float acc = 0.0f;
    #pragma unroll 16
    for (int k = 0; k < 128; k++) acc = fmaf(ms[k], Wm[k * D + t], acc);
    g_tg[b * D + t] = ftanh(acc);
}

// ---------------------------------------------------------------------------
// K3: coefs = sigmoid(<x2, tg[batch]>); out = segment_sum(coef * x2).
// Warp-per-row, 8-row groups, uniform fast path (R10 structure, unchanged).
// ---------------------------------------------------------------------------
__global__ void __launch_bounds__(256) k_out(
    const int* __restrict__ bw, float* __restrict__ out, int N, int rpw)
{
    int tid = threadIdx.x, lane = tid & 31;
    int warp = blockIdx.x * (blockDim.x >> 5) + (tid >> 5);
    long long r0l = (long long)warp * rpw;
    if (r0l >= N) return;
    int rs = (int)r0l;
    int re = min(N, rs + rpw);

    bool is64 = (g_is64 != 0);
    float4 acc = make_float4(0.f, 0.f, 0.f, 0.f);
    float4 tgv = make_float4(0.f, 0.f, 0.f, 0.f);
    int cur_b = -1;

    for (int r0 = rs; r0 < re; r0 += 8) {
        int m = min(8, re - r0);
        float4 xv[8]; int bb[8];
        #pragma unroll
        for (int q = 0; q < 8; q++) {
            int rr = r0 + q; if (rr >= re) rr = re - 1;
            bb[q] = is64 ? bw[2 * rr] : bw[rr];
            float2 u = __ldcs((const float2*)&g_x2h[(size_t)rr * D + lane * 4]);
            unsigned u0 = __float_as_uint(u.x), u1 = __float_as_uint(u.y);
            float2 f0 = __half22float2(*(__half2*)&u0);
            float2 f1 = __half22float2(*(__half2*)&u1);
            xv[q] = make_float4(f0.x, f0.y, f1.x, f1.y);
        }

        bool uni = (m == 8) & (bb[0] == cur_b) & (bb[7] == cur_b);
        if (uni) {
            float s[8];
            #pragma unroll
            for (int q = 0; q < 8; q++)
                s[q] = fmaf(xv[q].x, tgv.x, fmaf(xv[q].y, tgv.y,
                       fmaf(xv[q].z, tgv.z, xv[q].w * tgv.w)));
            #pragma unroll
            for (int off = 16; off >= 1; off >>= 1) {
                #pragma unroll
                for (int q = 0; q < 8; q++)
                    s[q] += __shfl_xor_sync(0xffffffffu, s[q], off);
            }
            #pragma unroll
            for (int q = 0; q < 8; q++) {
                float coef = fsigmoid(s[q]);
                acc.x = fmaf(coef, xv[q].x, acc.x);
                acc.y = fmaf(coef, xv[q].y, acc.y);
                acc.z = fmaf(coef, xv[q].z, acc.z);
                acc.w = fmaf(coef, xv[q].w, acc.w);
            }
        } else {
            #pragma unroll
            for (int q = 0; q < 8; q++) {
                if (q >= m) break;
                int b = bb[q];
                if (b != cur_b) {
                    if (cur_b >= 0) {
                        float* dst = &out[cur_b * D + lane * 4];
                        atomicAdd(dst + 0, acc.x);
                        atomicAdd(dst + 1, acc.y);
                        atomicAdd(dst + 2, acc.z);
                        atomicAdd(dst + 3, acc.w);
                    }
                    acc = make_float4(0.f, 0.f, 0.f, 0.f);
                    cur_b = b;
                    tgv = ((const float4*)g_tg)[b * 32 + lane];
                }
                float s = fmaf(xv[q].x, tgv.x, fmaf(xv[q].y, tgv.y,
                          fmaf(xv[q].z, tgv.z, xv[q].w * tgv.w)));
                #pragma unroll
                for (int off = 16; off >= 1; off >>= 1)
                    s += __shfl_xor_sync(0xffffffffu, s, off);
                float coef = fsigmoid(s);
                acc.x = fmaf(coef, xv[q].x, acc.x);
                acc.y = fmaf(coef, xv[q].y, acc.y);
                acc.z = fmaf(coef, xv[q].z, acc.z);
                acc.w = fmaf(coef, xv[q].w, acc.w);
            }
        }
    }
    if (cur_b >= 0) {
        float* dst = &out[cur_b * D + lane * 4];
        atomicAdd(dst + 0, acc.x);
        atomicAdd(dst + 1, acc.y);
        atomicAdd(dst + 2, acc.z);
        atomicAdd(dst + 3, acc.w);
    }
}

// ---------------------------------------------------------------------------
// Inputs (metadata order): x, batch, [size], Wm, fc1_w, fc1_b, fc2_w, fc2_b
// ---------------------------------------------------------------------------
extern "C" void kernel_launch(void* const* d_in, const int* in_sizes, int n_in,
                              void* d_out, int out_size)
{
    const float* x  = (const float*)d_in[0];
    const int*   bw = (const int*)d_in[1];
    int base = 2;
    if (n_in >= 8 && in_sizes[2] < 64) base = 3;   // scalar 'size' input present
    const float* Wm   = (const float*)d_in[base + 0];
    const float* fc1w = (const float*)d_in[base + 1];
    const float* fc1b = (const float*)d_in[base + 2];
    const float* fc2w = (const float*)d_in[base + 3];
    const float* fc2b = (const float*)d_in[base + 4];

    int N = in_sizes[0] / D;
    if (N > NMAX) N = NMAX;
    int B = out_size / D;
    if (B > BMAX) B = BMAX;
    float* out = (float*)d_out;

    k_init<<<256, 256>>>(out, out_size, B, bw, N);

    // k_mlp smem: 16KB frags + 5*2*16*132*4B x-stage + 5*16*72*2B x2-stage
    const size_t MSMEM = 2048 * sizeof(uint2)
                       + (size_t)5 * 2 * 16 * XS_STRIDE * sizeof(float)
                       + (size_t)5 * 16 * X2S_STRIDE * sizeof(__half);  // 112384 B
    static int attr_done = 0;
    if (!attr_done) {
        cudaFuncSetAttribute(k_mlp, cudaFuncAttributeMaxDynamicSharedMemorySize,
                             (int)MSMEM);
        attr_done = 1;
    }
    const int RPW = 344;   // 291 blocks <= 296 resident slots (148 SMs x 2)
    int warps = (N + RPW - 1) / RPW;
    int mblocks = (warps + 4) / 5;
    k_mlp<<<mblocks, 160, MSMEM>>>(x, bw, fc1w, fc1b, fc2w, fc2b, N, RPW);

    k_global<<<B, 128>>>(Wm, B);

    const int RPW_OUT = 64;
    int owarps = (N + RPW_OUT - 1) / RPW_OUT;
    int oblocks = (owarps + 7) / 8;
    k_out<<<oblocks, 256>>>(bw, out, N, RPW_OUT);
}